// round 14
// baseline (speedup 1.0000x reference)
#include <cuda_runtime.h>
#include <cuda_bf16.h>
#include <cstdint>

#define Bb    8
#define Nn    2048
#define Dd    512
#define HIDc  2048
#define DQK   128
#define GRP   256
#define Gg    8
#define NT    (Bb*Nn)
#define Ee    1024
#define KK    17

// ================= warp MMA / async helpers =================
__device__ __forceinline__ uint32_t smem_to_u32(const void* p) {
    uint32_t a;
    asm("{ .reg .u64 t; cvta.to.shared.u64 t, %1; cvt.u32.u64 %0, t; }" : "=r"(a) : "l"(p));
    return a;
}
__device__ __forceinline__ void ldsm4(uint32_t* r, uint32_t addr) {
    asm volatile("ldmatrix.sync.aligned.m8n8.x4.shared.b16 {%0,%1,%2,%3}, [%4];"
        : "=r"(r[0]), "=r"(r[1]), "=r"(r[2]), "=r"(r[3]) : "r"(addr));
}
__device__ __forceinline__ void mma16816(float* c, const uint32_t* a, uint32_t b0, uint32_t b1) {
    asm volatile(
        "mma.sync.aligned.m16n8k16.row.col.f32.bf16.bf16.f32 "
        "{%0,%1,%2,%3}, {%4,%5,%6,%7}, {%8,%9}, {%0,%1,%2,%3};"
        : "+f"(c[0]), "+f"(c[1]), "+f"(c[2]), "+f"(c[3])
        : "r"(a[0]), "r"(a[1]), "r"(a[2]), "r"(a[3]), "r"(b0), "r"(b1));
}
__device__ __forceinline__ void cp16(uint32_t dst, const void* src) {
    asm volatile("cp.async.cg.shared.global [%0], [%1], 16;" :: "r"(dst), "l"(src));
}
#define CP_COMMIT() asm volatile("cp.async.commit_group;" ::: "memory")
#define CP_WAIT(N)  asm volatile("cp.async.wait_group %0;" :: "n"(N) : "memory")

#define F_SILU  1
#define F_SCORE 4
#define F_TRIA  16
#define F_BF16  32

// ================= scratch pool =================
#define SZF(n) ((size_t)(n)*4)
#define SZB(n) ((size_t)(n)*2)
static constexpr size_t O_OPRE = 0;                                 // f32 [NT,512]
static constexpr size_t O_LNH  = O_OPRE + SZF((size_t)NT*512);      // bf16 [NT,1024]
static constexpr size_t O_WCAT = O_LNH  + SZB((size_t)NT*1024);     // bf16 [2176,512]
static constexpr size_t O_WOTH = O_WCAT + SZB(2176*512);            // bf16 [512,1024]
static constexpr size_t O_BCAT = O_WOTH + SZB(512*1024);            // f32 [2176]
static constexpr size_t O_BO   = O_BCAT + SZF(2176);                // f32 [512]
static constexpr size_t O_HB   = O_BO   + SZF(512);                 // bf16 [NT,2048] (h)
static constexpr size_t O_HID  = O_HB   + SZB((size_t)NT*2048);     // bf16 [NT,2048]
static constexpr size_t O_ATT  = O_HID  + SZB((size_t)NT*2048);     // bf16 [NT,2048]
static constexpr size_t O_HTH  = O_ATT  + SZB((size_t)NT*2048);     // bf16 [bg,2048,256]
static constexpr size_t O_QK   = O_HTH  + SZB((size_t)NT*2048);     // f32 [NT,128]
static constexpr size_t O_QQH  = O_QK   + SZF((size_t)NT*128);      // bf16 [NT,128] x3
static constexpr size_t O_LQH  = O_QQH  + SZB((size_t)NT*128);
static constexpr size_t O_QKH  = O_LQH  + SZB((size_t)NT*128);
static constexpr size_t O_LKF  = O_QKH  + SZB((size_t)NT*128);      // f32 [NT,128]
static constexpr size_t O_LKTH = O_LKF  + SZF((size_t)NT*128);      // bf16 [bg,128,256]
static constexpr size_t O_ATTH = O_LKTH + SZB((size_t)NT*128);      // bf16 [bg,256,256]
static constexpr size_t O_KVF  = O_ATTH + SZB((size_t)64*256*256);  // f32 [bg,2048,128]
static constexpr size_t O_KVH  = O_KVF  + SZF((size_t)64*2048*128); // bf16
static constexpr size_t O_END  = O_KVH  + SZB((size_t)64*2048*128);
__device__ __align__(1024) unsigned char g_pool[O_END];

__device__ __forceinline__ uint32_t pack_bf2(float v0, float v1) {
    __nv_bfloat16 h0 = __float2bfloat16(v0), h1 = __float2bfloat16(v1);
    return ((uint32_t)__bfloat16_as_ushort(h1) << 16) | __bfloat16_as_ushort(h0);
}
__device__ __forceinline__ void unpk4(uint2 u, float* f) {
    f[0] = __bfloat162float(__ushort_as_bfloat16((unsigned short)(u.x & 0xffff)));
    f[1] = __bfloat162float(__ushort_as_bfloat16((unsigned short)(u.x >> 16)));
    f[2] = __bfloat162float(__ushort_as_bfloat16((unsigned short)(u.y & 0xffff)));
    f[3] = __bfloat162float(__ushort_as_bfloat16((unsigned short)(u.y >> 16)));
}

// ================= prep kernels =================
__global__ void bias_fold_k(const float* __restrict__ W, const float* __restrict__ lnb,
                            const float* __restrict__ bias, float* __restrict__ out,
                            int K, int N) {
    int n = blockIdx.x;
    float s = 0.f;
    for (int k = threadIdx.x; k < K; k += blockDim.x)
        s += lnb[k] * W[(size_t)k*N + n];
    #pragma unroll
    for (int o = 16; o; o >>= 1) s += __shfl_xor_sync(~0u, s, o);
    __shared__ float sh[8];
    int w = threadIdx.x >> 5, l = threadIdx.x & 31;
    if (l == 0) sh[w] = s;
    __syncthreads();
    if (threadIdx.x == 0) {
        float ts = bias[n];
        for (int i = 0; i < (int)(blockDim.x >> 5); i++) ts += sh[i];
        out[n] = ts;
    }
}

// fused token-shift + pure-xhat LN (C=512) -> bf16
__global__ void ln_shift_k(const float* __restrict__ x, __nv_bfloat16* __restrict__ oh) {
    long t = blockIdx.x;
    int n = (int)(t % Nn);
    int i = threadIdx.x;
    const float2* xr = (const float2*)(x + t*Dd);
    const float2* xp = (const float2*)(x + (t-1)*Dd);
    float2 v;
    if (i < 128) v = (n == 0) ? make_float2(0.f, 0.f) : xp[i];
    else         v = xr[i];
    float s = v.x + v.y, s2 = v.x*v.x + v.y*v.y;
    #pragma unroll
    for (int o = 16; o; o >>= 1) {
        s  += __shfl_xor_sync(~0u, s,  o);
        s2 += __shfl_xor_sync(~0u, s2, o);
    }
    __shared__ float shs[8], shs2[8], smu, sinv;
    int w = i >> 5, l = i & 31;
    if (l == 0) { shs[w] = s; shs2[w] = s2; }
    __syncthreads();
    if (i == 0) {
        float ts = 0.f, ts2 = 0.f;
        for (int k = 0; k < 8; k++) { ts += shs[k]; ts2 += shs2[k]; }
        float mu = ts / Dd;
        smu = mu; sinv = rsqrtf(ts2 / Dd - mu*mu + 1e-5f);
    }
    __syncthreads();
    float mu = smu, inv = sinv;
    ((uint32_t*)(oh + t*Dd))[i] = pack_bf2((v.x - mu)*inv, (v.y - mu)*inv);
}

// fused gating + pure-xhat LN(1024), bf16 in -> bf16 out. 256 thr, 4 ch/thread.
__global__ void gate_ln_k(const __nv_bfloat16* __restrict__ att,
                          const __nv_bfloat16* __restrict__ hid,
                          __nv_bfloat16* __restrict__ oh) {
    long row = blockIdx.x;
    int i = threadIdx.x;
    float av[4], au[4], v[4], u[4], t[4];
    unpk4(((const uint2*)(att + row*HIDc))[i],      av);
    unpk4(((const uint2*)(att + row*HIDc + Ee))[i], au);
    unpk4(((const uint2*)(hid + row*HIDc))[i],      v);
    unpk4(((const uint2*)(hid + row*HIDc + Ee))[i], u);
    float s = 0.f, s2 = 0.f;
    #pragma unroll
    for (int j = 0; j < 4; j++) {
        t[j] = au[j] * v[j] * (1.f / (1.f + expf(-(av[j] * u[j]))));
        s += t[j]; s2 += t[j]*t[j];
    }
    #pragma unroll
    for (int o = 16; o; o >>= 1) {
        s  += __shfl_xor_sync(~0u, s,  o);
        s2 += __shfl_xor_sync(~0u, s2, o);
    }
    __shared__ float shs[8], shs2[8], smu, sinv;
    int w = i >> 5, l = i & 31;
    if (l == 0) { shs[w] = s; shs2[w] = s2; }
    __syncthreads();
    if (i == 0) {
        float ts = 0.f, ts2 = 0.f;
        for (int k = 0; k < 8; k++) { ts += shs[k]; ts2 += shs2[k]; }
        float mu = ts / 1024.f;
        smu = mu; sinv = rsqrtf(ts2 / 1024.f - mu*mu + 1e-5f);
    }
    __syncthreads();
    float mu = smu, inv = sinv;
    ((uint2*)(oh + row*1024))[i] = make_uint2(
        pack_bf2((t[0]-mu)*inv, (t[1]-mu)*inv),
        pack_bf2((t[2]-mu)*inv, (t[3]-mu)*inv));
}

// transpose fp32 [R,C] -> bf16 [C,R], optional per-input-row gain, batched via z
__global__ void trans_bf16_k(const float* __restrict__ in,
                             __nv_bfloat16* __restrict__ oh, int R, int C,
                             const float* __restrict__ gain) {
    __shared__ float s[32][36];
    size_t bz = (size_t)blockIdx.z * R * C;
    int c0 = blockIdx.x * 32, r0 = blockIdx.y * 32;
    int t = threadIdx.x;
    {
        int r = t >> 3, c4 = (t & 7) * 4;
        float4 v = *(const float4*)(in + bz + (size_t)(r0 + r)*C + c0 + c4);
        if (gain) {
            float gv = gain[r0 + r];
            v.x *= gv; v.y *= gv; v.z *= gv; v.w *= gv;
        }
        *(float4*)&s[r][c4] = v;
    }
    __syncthreads();
    {
        int c = t & 31, rg = (t >> 5) * 4;
        uint32_t h01 = pack_bf2(s[rg][c],   s[rg+1][c]);
        uint32_t h23 = pack_bf2(s[rg+2][c], s[rg+3][c]);
        size_t o = bz + (size_t)(c0 + c)*R + r0 + rg;
        *(uint2*)(oh + o) = make_uint2(h01, h23);
    }
}

// depthwise conv K=17 + residual, bf16 in/out (C=2048), fused group-transpose -> ht
__global__ void dwconv_bf16_k(const __nv_bfloat16* __restrict__ h, const float* __restrict__ dw,
                              __nv_bfloat16* __restrict__ out, __nv_bfloat16* __restrict__ ht) {
    const int C = HIDc, NTile = 128, HALO = 8;
    __shared__ float sh[144][68];
    __shared__ float sdw[KK][64];
    int b = blockIdx.z, n0 = blockIdx.y * NTile, c0 = blockIdx.x * 64;
    for (int idx = threadIdx.x; idx < 144*8; idx += 256) {
        int r = idx >> 3, c8 = (idx & 7) * 8;
        int n = n0 - HALO + r;
        if (n >= 0 && n < Nn) {
            uint4 uv = *(const uint4*)(h + ((size_t)b*Nn + n)*C + c0 + c8);
            const uint32_t* up = (const uint32_t*)&uv;
            #pragma unroll
            for (int j = 0; j < 4; j++) {
                sh[r][c8 + 2*j]   = __bfloat162float(__ushort_as_bfloat16((unsigned short)(up[j] & 0xffff)));
                sh[r][c8 + 2*j+1] = __bfloat162float(__ushort_as_bfloat16((unsigned short)(up[j] >> 16)));
            }
        } else {
            #pragma unroll
            for (int j = 0; j < 8; j++) sh[r][c8 + j] = 0.f;
        }
    }
    for (int idx = threadIdx.x; idx < KK*64; idx += 256)
        sdw[idx >> 6][idx & 63] = dw[(idx >> 6)*C + c0 + (idx & 63)];
    __syncthreads();
    float res[4][8];
    #pragma unroll
    for (int e = 0; e < 4; e++) {
        int idx = threadIdx.x + e*256;          // 0..1023 over 128 rows x 8 ch-octs
        int r = idx >> 3, c8 = (idx & 7) * 8;
        #pragma unroll
        for (int j = 0; j < 8; j++) res[e][j] = sh[r + HALO][c8 + j];
        #pragma unroll
        for (int k = 0; k < KK; k++)
            #pragma unroll
            for (int j = 0; j < 8; j++)
                res[e][j] += sh[r + k][c8 + j] * sdw[k][c8 + j];
        uint4 o;
        uint32_t* op = (uint32_t*)&o;
        #pragma unroll
        for (int j = 0; j < 4; j++) op[j] = pack_bf2(res[e][2*j], res[e][2*j+1]);
        *(uint4*)(out + ((size_t)b*Nn + n0 + r)*C + c0 + c8) = o;
    }
    // stage results for group-transpose (stride 65)
    __syncthreads();
    float* sout = (float*)sh;
    #pragma unroll
    for (int e = 0; e < 4; e++) {
        int idx = threadIdx.x + e*256;
        int r = idx >> 3, c8 = (idx & 7) * 8;
        #pragma unroll
        for (int j = 0; j < 8; j++) sout[r*65 + c8 + j] = res[e][j];
    }
    __syncthreads();
    int g = n0 >> 8, nloc = n0 & 255;
    size_t basebg = ((size_t)(b*Gg + g)*C + c0) * 256 + nloc;
    #pragma unroll
    for (int e = 0; e < 8; e++) {
        int idx = threadIdx.x + e*256;          // 64 ch x 32 quads
        int cc = idx >> 5, r4 = (idx & 31) * 4;
        float v0 = sout[(r4+0)*65 + cc];
        float v1 = sout[(r4+1)*65 + cc];
        float v2 = sout[(r4+2)*65 + cc];
        float v3 = sout[(r4+3)*65 + cc];
        *(uint2*)(ht + basebg + (size_t)cc*256 + r4) =
            make_uint2(pack_bf2(v0, v1), pack_bf2(v2, v3));
    }
}

// f32 depthwise conv K=17 + residual (+ extra residual) — qk/final paths
__global__ void dwconv4_k(const float4* __restrict__ h4, const float* __restrict__ dw,
                          const float4* __restrict__ extra4, float4* __restrict__ out4, int C) {
    const int CT4 = 16, NTile = 128, HALO = 8;
    __shared__ float4 sh[NTile + 2*HALO][CT4];
    __shared__ float4 sdw[KK][CT4];
    int b = blockIdx.z, n0 = blockIdx.y * NTile, c0 = blockIdx.x * CT4;
    int C4 = C >> 2;
    const float4* base = h4 + (size_t)b*Nn*C4 + c0;
    for (int idx = threadIdx.x; idx < (NTile + 2*HALO)*CT4; idx += blockDim.x) {
        int r = idx >> 4, c = idx & 15;
        int n = n0 - HALO + r;
        sh[r][c] = (n >= 0 && n < Nn) ? base[(size_t)n*C4 + c] : make_float4(0,0,0,0);
    }
    for (int idx = threadIdx.x; idx < KK*CT4; idx += blockDim.x) {
        int k = idx >> 4, c = idx & 15;
        const float* w = dw + k*C + (c0 + c)*4;
        sdw[k][c] = make_float4(w[0], w[1], w[2], w[3]);
    }
    __syncthreads();
    for (int idx = threadIdx.x; idx < NTile*CT4; idx += blockDim.x) {
        int r = idx >> 4, c = idx & 15;
        float4 acc = sh[r + HALO][c];
        #pragma unroll
        for (int k = 0; k < KK; k++) {
            float4 a = sh[r + k][c], w = sdw[k][c];
            acc.x += a.x*w.x; acc.y += a.y*w.y; acc.z += a.z*w.z; acc.w += a.w*w.w;
        }
        size_t o = (size_t)b*Nn*C4 + (size_t)(n0 + r)*C4 + c0 + c;
        if (extra4) {
            float4 ev = extra4[o];
            acc.x += ev.x; acc.y += ev.y; acc.z += ev.z; acc.w += ev.w;
        }
        out4[o] = acc;
    }
}

// dwconv (C=128) + residual, fused offset-scale split epilogue
__global__ void dwconv_qsplit_k(const float4* __restrict__ h4, const float* __restrict__ dw,
                                const float* __restrict__ gamma, const float* __restrict__ beta,
                                __nv_bfloat16* __restrict__ qqh, __nv_bfloat16* __restrict__ lqh,
                                __nv_bfloat16* __restrict__ qkh, float* __restrict__ lkf) {
    const int CT4 = 16, NTile = 128, HALO = 8, C4 = 32;
    __shared__ float4 sh[NTile + 2*HALO][CT4];
    __shared__ float4 sdw[KK][CT4];
    __shared__ float sg[4][64], sb[4][64];
    int b = blockIdx.z, n0 = blockIdx.y * NTile, c0 = blockIdx.x * CT4;
    const float4* base = h4 + (size_t)b*Nn*C4 + c0;
    for (int idx = threadIdx.x; idx < (NTile + 2*HALO)*CT4; idx += blockDim.x) {
        int r = idx >> 4, c = idx & 15;
        int n = n0 - HALO + r;
        sh[r][c] = (n >= 0 && n < Nn) ? base[(size_t)n*C4 + c] : make_float4(0,0,0,0);
    }
    for (int idx = threadIdx.x; idx < KK*CT4; idx += blockDim.x) {
        int k = idx >> 4, c = idx & 15;
        const float* w = dw + k*DQK + (c0 + c)*4;
        sdw[k][c] = make_float4(w[0], w[1], w[2], w[3]);
    }
    {
        int s = threadIdx.x >> 6, j = threadIdx.x & 63;
        sg[s][j] = gamma[s*DQK + c0*4 + j];
        sb[s][j] = beta [s*DQK + c0*4 + j];
    }
    __syncthreads();
    #pragma unroll
    for (int e = 0; e < 8; e++) {
        int idx = threadIdx.x + e*256;
        int r = idx >> 4, c = idx & 15;
        float4 acc = sh[r + HALO][c];
        #pragma unroll
        for (int k = 0; k < KK; k++) {
            float4 a = sh[r + k][c], w = sdw[k][c];
            acc.x += a.x*w.x; acc.y += a.y*w.y; acc.z += a.z*w.z; acc.w += a.w*w.w;
        }
        float av[4] = {acc.x, acc.y, acc.z, acc.w};
        int chl = c*4;
        float q[4], lq[4], qk[4], lk[4];
        #pragma unroll
        for (int j = 0; j < 4; j++) {
            q[j]  = av[j]*sg[0][chl+j] + sb[0][chl+j];
            lq[j] = av[j]*sg[1][chl+j] + sb[1][chl+j];
            qk[j] = av[j]*sg[2][chl+j] + sb[2][chl+j];
            lk[j] = av[j]*sg[3][chl+j] + sb[3][chl+j];
        }
        size_t ob = ((size_t)b*Nn + n0 + r)*DQK + (c0 + c)*4;
        *(uint2*)(qqh + ob) = make_uint2(pack_bf2(q[0],q[1]),  pack_bf2(q[2],q[3]));
        *(uint2*)(lqh + ob) = make_uint2(pack_bf2(lq[0],lq[1]), pack_bf2(lq[2],lq[3]));
        *(uint2*)(qkh + ob) = make_uint2(pack_bf2(qk[0],qk[1]), pack_bf2(qk[2],qk[3]));
        *(float4*)(lkf + ob) = make_float4(lk[0], lk[1], lk[2], lk[3]);
    }
}

__global__ void cumsum_bf16_k(const float* __restrict__ kvf,
                              __nv_bfloat16* __restrict__ oh) {
    const size_t S = (size_t)2048*128;
    long i2 = (long)blockIdx.x * blockDim.x + threadIdx.x;
    if (i2 >= (long)Bb*(S/2)) return;
    size_t b = (size_t)i2 / (S/2), r2 = (size_t)i2 % (S/2);
    size_t base2 = b*Gg*(S/2) + r2;
    float s0 = 0.f, s1 = 0.f;
    #pragma unroll
    for (int g = 0; g < Gg; g++) {
        size_t o2 = base2 + (size_t)g*(S/2);
        float2 v = ((const float2*)kvf)[o2];
        ((uint32_t*)oh)[o2] = pack_bf2(s0, s1);
        s0 += v.x; s1 += v.y;
    }
}

// ================= HMMA bf16 GEMM — two-part K, split-C, bf16-out option ========
#define LDA 72
#define STG_BYTES 36864
#define GSMEM (2*STG_BYTES)

__global__ void __launch_bounds__(256, 2) gemm_k(
    const __nv_bfloat16* __restrict__ A1, const __nv_bfloat16* __restrict__ B1,
    const __nv_bfloat16* __restrict__ A2, const __nv_bfloat16* __restrict__ B2,
    float* C, float* Cq, __nv_bfloat16* Ch,
    int M, int N, int K1, int K2, const float* __restrict__ bias, float alpha, int flags,
    long long sA1, long long sB1, long long sA2, long long sB2, long long sC)
{
    extern __shared__ __align__(16) unsigned char smem[];
    uint32_t sbase = smem_to_u32(smem);
    int tid = threadIdx.x, lane = tid & 31, wid = tid >> 5;
    int wm = wid & 3, wn = wid >> 2;
    int brow = blockIdx.y * 128, bcol = blockIdx.x * 128;
    long long bz = blockIdx.z;
    A1 += bz*sA1; B1 += bz*sB1;
    if (A2) { A2 += bz*sA2; B2 += bz*sB2; }
    if (C)  C  += bz*sC;
    if (Ch) Ch += bz*sC;

    if ((flags & F_SCORE) && bcol > brow) {
        uint4 z = make_uint4(0,0,0,0);
        for (int e = tid; e < 2048; e += 256) {
            int row = e >> 4, seg = e & 15;
            *(uint4*)(Ch + (size_t)(brow + row)*N + bcol + seg*8) = z;
        }
        return;
    }

    float acc[2][8][4];
    #pragma unroll
    for (int i = 0; i < 2; i++)
        #pragma unroll
        for (int j = 0; j < 8; j++)
            #pragma unroll
            for (int q = 0; q < 4; q++) acc[i][j][q] = 0.f;

    uint32_t aOff = (uint32_t)(((wm*32 + (lane & 15)) * LDA + (lane >> 4)*8) * 2);
    uint32_t bOff = (uint32_t)(((wn*64 + ((lane >> 4) & 1)*8 + (lane & 7)) * LDA
                                + ((lane >> 3) & 1)*8) * 2) + 18432;
    const int ldr = tid >> 3, lds2 = tid & 7;

    int KC1 = K1 >> 6;
    if (flags & F_TRIA) {
        int kc = (brow + 128) >> 6;
        if (kc < KC1) KC1 = kc;
    }
    const int KC2 = K2 >> 6;
    const int KC = KC1 + KC2;

    auto issue = [&](int it) {
        const __nv_bfloat16 *Ap, *Bp; int k0, Kst;
        if (it < KC1) { Ap = A1; Bp = B1; k0 = it << 6;          Kst = K1; }
        else          { Ap = A2; Bp = B2; k0 = (it - KC1) << 6;  Kst = K2; }
        uint32_t sa = sbase + (uint32_t)(it & 1)*STG_BYTES;
        #pragma unroll
        for (int e = 0; e < 4; e++) {
            int r = ldr + e*32;
            cp16(sa + (uint32_t)(r*144 + lds2*16),
                 Ap + (size_t)(brow + r)*Kst + k0 + lds2*8);
            cp16(sa + 18432u + (uint32_t)(r*144 + lds2*16),
                 Bp + (size_t)(bcol + r)*Kst + k0 + lds2*8);
        }
        CP_COMMIT();
    };

    issue(0);
    for (int it = 0; it < KC; ++it) {
        if (it + 1 < KC) { issue(it + 1); CP_WAIT(1); }
        else             { CP_WAIT(0); }
        __syncthreads();
        uint32_t stg = sbase + (uint32_t)(it & 1)*STG_BYTES;
        uint32_t aB = stg + aOff, bB = stg + bOff;
        #pragma unroll
        for (int kk = 0; kk < 4; kk++) {
            uint32_t af[2][4], bfr[4][4];
            #pragma unroll
            for (int i = 0; i < 2; i++)
                ldsm4(af[i], aB + (uint32_t)((i*16*LDA + kk*16) * 2));
            #pragma unroll
            for (int p = 0; p < 4; p++)
                ldsm4(bfr[p], bB + (uint32_t)((p*16*LDA + kk*16) * 2));
            #pragma unroll
            for (int i = 0; i < 2; i++)
                #pragma unroll
                for (int j = 0; j < 8; j++)
                    mma16816(acc[i][j], af[i], bfr[j>>1][(j&1)*2], bfr[j>>1][(j&1)*2+1]);
        }
        __syncthreads();
    }

    // ---- epilogue ----
    int g = lane >> 2, c2 = (lane & 3)*2;
    #pragma unroll
    for (int i = 0; i < 2; i++) {
        #pragma unroll
        for (int j = 0; j < 8; j++) {
            #pragma unroll
            for (int rr = 0; rr < 2; rr++) {
                int row = brow + wm*32 + i*16 + g + rr*8;
                int col = bcol + wn*64 + j*8 + c2;
                float v0 = acc[i][j][rr*2+0] * alpha;
                float v1 = acc[i][j][rr*2+1] * alpha;
                if (flags & F_SCORE) {
                    v0 = fmaxf(v0, 0.f); v0 *= v0;
                    v1 = fmaxf(v1, 0.f); v1 *= v1;
                    if (col     > row) v0 = 0.f;
                    if (col + 1 > row) v1 = 0.f;
                    *(uint32_t*)(Ch + (size_t)row*N + col) = pack_bf2(v0, v1);
                } else {
                    if (bias) { v0 += bias[col]; v1 += bias[col+1]; }
                    if (flags & F_SILU) {
                        v0 = v0 / (1.f + expf(-v0));
                        v1 = v1 / (1.f + expf(-v1));
                    }
                    if (Cq && col >= 2048) {
                        *(float2*)(Cq + (size_t)row*DQK + col - 2048) = make_float2(v0, v1);
                    } else if (flags & F_BF16) {
                        *(uint32_t*)(Ch + (size_t)row*N + col) = pack_bf2(v0, v1);
                    } else {
                        *(float2*)(C + (size_t)row*N + col) = make_float2(v0, v1);
                    }
                }
            }
        }
    }
}

// ================= launcher =================
extern "C" void kernel_launch(void* const* d_in, const int* in_sizes, int n_in,
                              void* d_out, int out_size) {
    const float* x      = (const float*)d_in[0];
    const float* ln_h_g = (const float*)d_in[1];
    const float* ln_h_b = (const float*)d_in[2];
    const float* W_h    = (const float*)d_in[3];
    const float* b_h    = (const float*)d_in[4];
    const float* dw_h   = (const float*)d_in[5];
    const float* ln_qk_g= (const float*)d_in[6];
    const float* ln_qk_b= (const float*)d_in[7];
    const float* W_qk   = (const float*)d_in[8];
    const float* b_qk   = (const float*)d_in[9];
    const float* dw_qk  = (const float*)d_in[10];
    const float* gamma  = (const float*)d_in[11];
    const float* beta   = (const float*)d_in[12];
    const float* ln_o_g = (const float*)d_in[13];
    const float* ln_o_b = (const float*)d_in[14];
    const float* W_o    = (const float*)d_in[15];
    const float* b_o    = (const float*)d_in[16];
    const float* dw_o   = (const float*)d_in[17];
    float* out = (float*)d_out;

    unsigned char* pool;
    cudaGetSymbolAddress((void**)&pool, g_pool);
    float*         opre = (float*)(pool + O_OPRE);
    __nv_bfloat16* lnH  = (__nv_bfloat16*)(pool + O_LNH);
    __nv_bfloat16* wCat = (__nv_bfloat16*)(pool + O_WCAT);
    __nv_bfloat16* woTH = (__nv_bfloat16*)(pool + O_WOTH);
    float*         bCat = (float*)(pool + O_BCAT);
    float*         bO   = (float*)(pool + O_BO);
    __nv_bfloat16* hB   = (__nv_bfloat16*)(pool + O_HB);
    __nv_bfloat16* hid  = (__nv_bfloat16*)(pool + O_HID);
    __nv_bfloat16* attB = (__nv_bfloat16*)(pool + O_ATT);
    __nv_bfloat16* hTH  = (__nv_bfloat16*)(pool + O_HTH);
    float*         qk   = (float*)(pool + O_QK);
    __nv_bfloat16* qqH  = (__nv_bfloat16*)(pool + O_QQH);
    __nv_bfloat16* lqH  = (__nv_bfloat16*)(pool + O_LQH);
    __nv_bfloat16* qkH  = (__nv_bfloat16*)(pool + O_QKH);
    float*         lkF  = (float*)(pool + O_LKF);
    __nv_bfloat16* lkTH = (__nv_bfloat16*)(pool + O_LKTH);
    __nv_bfloat16* attH = (__nv_bfloat16*)(pool + O_ATTH);
    float*         kvF  = (float*)(pool + O_KVF);
    __nv_bfloat16* kvH  = (__nv_bfloat16*)(pool + O_KVH);

    cudaFuncSetAttribute(gemm_k, cudaFuncAttributeMaxDynamicSharedMemorySize, GSMEM);

    // 1. weight transposes with LN-gain folding
    trans_bf16_k<<<dim3(2048/32, 512/32, 1), 256>>>(W_h,  wCat,            512, 2048, ln_h_g);
    trans_bf16_k<<<dim3(128/32,  512/32, 1), 256>>>(W_qk, wCat + 2048*512, 512, 128,  ln_qk_g);
    trans_bf16_k<<<dim3(512/32, 1024/32, 1), 256>>>(W_o,  woTH,            1024, 512, ln_o_g);
    // 2. effective biases
    bias_fold_k<<<2048, 256>>>(W_h,  ln_h_b,  b_h,  bCat,        512, 2048);
    bias_fold_k<<<128,  256>>>(W_qk, ln_qk_b, b_qk, bCat + 2048, 512, 128);
    bias_fold_k<<<512,  256>>>(W_o,  ln_o_b,  b_o,  bO,          1024, 512);
    // 3. fused shift + pure-xhat LN -> lnH
    ln_shift_k<<<NT, 256>>>(x, lnH);
    // 4. MERGED GEMM1+GEMM2 -> hB (bf16) / qk (f32), SiLU
    gemm_k<<<dim3(17, 128, 1), 256, GSMEM>>>(lnH, wCat, nullptr, nullptr, nullptr, qk, hB,
        NT, HIDc, Dd, 0, bCat, 1.f, F_SILU | F_BF16, 0, 0, 0, 0, 0);
    // 5. dwconv (bf16) -> hid, fused group-transpose -> hTH
    dwconv_bf16_k<<<dim3(32, 16, Bb), 256>>>(hB, dw_h, hid, hTH);
    // 6. dwconv(C=128) + fused offset-scale split
    dwconv_qsplit_k<<<dim3(2, 16, Bb), 256>>>((const float4*)qk, dw_qk, gamma, beta,
                                              qqH, lqH, qkH, lkF);
    // 7. lin_k per-group transpose -> lkT [bg,128,256]
    trans_bf16_k<<<dim3(4, 8, 64), 256>>>(lkF, lkTH, 256, 128, nullptr);
    // 8. scores -> attH (relu^2 causal)
    gemm_k<<<dim3(2, 2, 64), 256, GSMEM>>>(qqH, qkH, nullptr, nullptr, nullptr, nullptr, attH,
        GRP, GRP, DQK, 0, nullptr, 1.f/GRP, F_SCORE,
        (long long)GRP*DQK, (long long)GRP*DQK, 0, 0, (long long)GRP*GRP);
    // 9. lin kv (coalesced)
    gemm_k<<<dim3(1, 16, 64), 256, GSMEM>>>(hTH, lkTH, nullptr, nullptr, kvF, nullptr, nullptr,
        HIDc, DQK, GRP, 0, nullptr, 1.f/GRP, 0,
        (long long)HIDc*GRP, (long long)DQK*GRP, 0, 0, (long long)HIDc*DQK);
    // 10. exclusive group cumsum -> kvH
    cumsum_bf16_k<<<(int)(((size_t)Bb*2048*64 + 255)/256), 256>>>(kvF, kvH);
    // 11. MERGED quad-out + lin-out -> attB (bf16)
    gemm_k<<<dim3(16, 2, 64), 256, GSMEM>>>(attH, hTH, lqH, kvH, nullptr, nullptr, attB,
        GRP, HIDc, GRP, DQK, nullptr, 1.f, F_TRIA | F_BF16,
        (long long)GRP*GRP, (long long)HIDc*GRP,
        (long long)GRP*DQK, (long long)HIDc*DQK, (long long)GRP*HIDc);
    // 12. fused gating (bf16 in) + pure-xhat LN_o -> lnH
    gate_ln_k<<<NT, 256>>>(attB, hid, lnH);
    // 13. GEMM3 -> opre (f32, SiLU, folded gains/bias)
    gemm_k<<<dim3(4, 128, 1), 256, GSMEM>>>(lnH, woTH, nullptr, nullptr, opre, nullptr, nullptr,
        NT, Dd, 2*Dd, 0, bO, 1.f, F_SILU, 0, 0, 0, 0, 0);
    // 14. dwconv + x residual -> out (f32)
    dwconv4_k<<<dim3(8, 16, Bb), 256>>>((const float4*)opre, dw_o, (const float4*)x,
                                        (float4*)out, Dd);
}

// round 15
// speedup vs baseline: 1.1358x; 1.1358x over previous
#include <cuda_runtime.h>
#include <cuda_bf16.h>
#include <cstdint>

#define Bb    8
#define Nn    2048
#define Dd    512
#define HIDc  2048
#define DQK   128
#define GRP   256
#define Gg    8
#define NT    (Bb*Nn)
#define Ee    1024
#define KK    17

// ================= warp MMA / async helpers =================
__device__ __forceinline__ uint32_t smem_to_u32(const void* p) {
    uint32_t a;
    asm("{ .reg .u64 t; cvta.to.shared.u64 t, %1; cvt.u32.u64 %0, t; }" : "=r"(a) : "l"(p));
    return a;
}
__device__ __forceinline__ void ldsm4(uint32_t* r, uint32_t addr) {
    asm volatile("ldmatrix.sync.aligned.m8n8.x4.shared.b16 {%0,%1,%2,%3}, [%4];"
        : "=r"(r[0]), "=r"(r[1]), "=r"(r[2]), "=r"(r[3]) : "r"(addr));
}
__device__ __forceinline__ void mma16816(float* c, const uint32_t* a, uint32_t b0, uint32_t b1) {
    asm volatile(
        "mma.sync.aligned.m16n8k16.row.col.f32.bf16.bf16.f32 "
        "{%0,%1,%2,%3}, {%4,%5,%6,%7}, {%8,%9}, {%0,%1,%2,%3};"
        : "+f"(c[0]), "+f"(c[1]), "+f"(c[2]), "+f"(c[3])
        : "r"(a[0]), "r"(a[1]), "r"(a[2]), "r"(a[3]), "r"(b0), "r"(b1));
}
__device__ __forceinline__ void cp16(uint32_t dst, const void* src) {
    asm volatile("cp.async.cg.shared.global [%0], [%1], 16;" :: "r"(dst), "l"(src));
}
#define CP_COMMIT() asm volatile("cp.async.commit_group;" ::: "memory")
#define CP_WAIT(N)  asm volatile("cp.async.wait_group %0;" :: "n"(N) : "memory")

#define F_SILU  1
#define F_SCORE 4
#define F_TRIA  16
#define F_BF16  32

// ================= scratch pool =================
#define SZF(n) ((size_t)(n)*4)
#define SZB(n) ((size_t)(n)*2)
static constexpr size_t O_OPRE = 0;                                 // f32 [NT,512]
static constexpr size_t O_LNH  = O_OPRE + SZF((size_t)NT*512);      // bf16 [NT,1024]
static constexpr size_t O_WCAT = O_LNH  + SZB((size_t)NT*1024);     // bf16 [2176,512]
static constexpr size_t O_WOTH = O_WCAT + SZB(2176*512);            // bf16 [512,1024]
static constexpr size_t O_BCAT = O_WOTH + SZB(512*1024);            // f32 [2176]
static constexpr size_t O_BO   = O_BCAT + SZF(2176);                // f32 [512]
static constexpr size_t O_HB   = O_BO   + SZF(512);                 // bf16 [NT,2048] (h)
static constexpr size_t O_HID  = O_HB   + SZB((size_t)NT*2048);     // bf16 [NT,2048]
static constexpr size_t O_ATT  = O_HID  + SZB((size_t)NT*2048);     // bf16 [NT,2048]
static constexpr size_t O_HTH  = O_ATT  + SZB((size_t)NT*2048);     // bf16 [bg,2048,256]
static constexpr size_t O_QK   = O_HTH  + SZB((size_t)NT*2048);     // f32 [NT,128]
static constexpr size_t O_QQH  = O_QK   + SZF((size_t)NT*128);      // bf16 [NT,128] x3
static constexpr size_t O_LQH  = O_QQH  + SZB((size_t)NT*128);
static constexpr size_t O_QKH  = O_LQH  + SZB((size_t)NT*128);
static constexpr size_t O_LKF  = O_QKH  + SZB((size_t)NT*128);      // f32 [NT,128]
static constexpr size_t O_LKTH = O_LKF  + SZF((size_t)NT*128);      // bf16 [bg,128,256]
static constexpr size_t O_ATTH = O_LKTH + SZB((size_t)NT*128);      // bf16 [bg,256,256]
static constexpr size_t O_KVF  = O_ATTH + SZB((size_t)64*256*256);  // f32 [bg,2048,128]
static constexpr size_t O_KVH  = O_KVF  + SZF((size_t)64*2048*128); // bf16
static constexpr size_t O_END  = O_KVH  + SZB((size_t)64*2048*128);
__device__ __align__(1024) unsigned char g_pool[O_END];

__device__ __forceinline__ uint32_t pack_bf2(float v0, float v1) {
    __nv_bfloat16 h0 = __float2bfloat16(v0), h1 = __float2bfloat16(v1);
    return ((uint32_t)__bfloat16_as_ushort(h1) << 16) | __bfloat16_as_ushort(h0);
}
__device__ __forceinline__ void unpk4(uint2 u, float* f) {
    f[0] = __bfloat162float(__ushort_as_bfloat16((unsigned short)(u.x & 0xffff)));
    f[1] = __bfloat162float(__ushort_as_bfloat16((unsigned short)(u.x >> 16)));
    f[2] = __bfloat162float(__ushort_as_bfloat16((unsigned short)(u.y & 0xffff)));
    f[3] = __bfloat162float(__ushort_as_bfloat16((unsigned short)(u.y >> 16)));
}

// ================= prep kernels =================
__global__ void bias_fold_k(const float* __restrict__ W, const float* __restrict__ lnb,
                            const float* __restrict__ bias, float* __restrict__ out,
                            int K, int N) {
    int n = blockIdx.x;
    float s = 0.f;
    for (int k = threadIdx.x; k < K; k += blockDim.x)
        s += lnb[k] * W[(size_t)k*N + n];
    #pragma unroll
    for (int o = 16; o; o >>= 1) s += __shfl_xor_sync(~0u, s, o);
    __shared__ float sh[8];
    int w = threadIdx.x >> 5, l = threadIdx.x & 31;
    if (l == 0) sh[w] = s;
    __syncthreads();
    if (threadIdx.x == 0) {
        float ts = bias[n];
        for (int i = 0; i < (int)(blockDim.x >> 5); i++) ts += sh[i];
        out[n] = ts;
    }
}

// fused token-shift + pure-xhat LN (C=512) -> bf16
__global__ void ln_shift_k(const float* __restrict__ x, __nv_bfloat16* __restrict__ oh) {
    long t = blockIdx.x;
    int n = (int)(t % Nn);
    int i = threadIdx.x;
    const float2* xr = (const float2*)(x + t*Dd);
    const float2* xp = (const float2*)(x + (t-1)*Dd);
    float2 v;
    if (i < 128) v = (n == 0) ? make_float2(0.f, 0.f) : xp[i];
    else         v = xr[i];
    float s = v.x + v.y, s2 = v.x*v.x + v.y*v.y;
    #pragma unroll
    for (int o = 16; o; o >>= 1) {
        s  += __shfl_xor_sync(~0u, s,  o);
        s2 += __shfl_xor_sync(~0u, s2, o);
    }
    __shared__ float shs[8], shs2[8], smu, sinv;
    int w = i >> 5, l = i & 31;
    if (l == 0) { shs[w] = s; shs2[w] = s2; }
    __syncthreads();
    if (i == 0) {
        float ts = 0.f, ts2 = 0.f;
        for (int k = 0; k < 8; k++) { ts += shs[k]; ts2 += shs2[k]; }
        float mu = ts / Dd;
        smu = mu; sinv = rsqrtf(ts2 / Dd - mu*mu + 1e-5f);
    }
    __syncthreads();
    float mu = smu, inv = sinv;
    ((uint32_t*)(oh + t*Dd))[i] = pack_bf2((v.x - mu)*inv, (v.y - mu)*inv);
}

// fused gating + pure-xhat LN(1024), bf16 in -> bf16 out
__global__ void gate_ln_k(const __nv_bfloat16* __restrict__ att,
                          const __nv_bfloat16* __restrict__ hid,
                          __nv_bfloat16* __restrict__ oh) {
    long row = blockIdx.x;
    int i = threadIdx.x;
    float av[4], au[4], v[4], u[4], t[4];
    unpk4(((const uint2*)(att + row*HIDc))[i],      av);
    unpk4(((const uint2*)(att + row*HIDc + Ee))[i], au);
    unpk4(((const uint2*)(hid + row*HIDc))[i],      v);
    unpk4(((const uint2*)(hid + row*HIDc + Ee))[i], u);
    float s = 0.f, s2 = 0.f;
    #pragma unroll
    for (int j = 0; j < 4; j++) {
        t[j] = au[j] * v[j] * (1.f / (1.f + expf(-(av[j] * u[j]))));
        s += t[j]; s2 += t[j]*t[j];
    }
    #pragma unroll
    for (int o = 16; o; o >>= 1) {
        s  += __shfl_xor_sync(~0u, s,  o);
        s2 += __shfl_xor_sync(~0u, s2, o);
    }
    __shared__ float shs[8], shs2[8], smu, sinv;
    int w = i >> 5, l = i & 31;
    if (l == 0) { shs[w] = s; shs2[w] = s2; }
    __syncthreads();
    if (i == 0) {
        float ts = 0.f, ts2 = 0.f;
        for (int k = 0; k < 8; k++) { ts += shs[k]; ts2 += shs2[k]; }
        float mu = ts / 1024.f;
        smu = mu; sinv = rsqrtf(ts2 / 1024.f - mu*mu + 1e-5f);
    }
    __syncthreads();
    float mu = smu, inv = sinv;
    ((uint2*)(oh + row*1024))[i] = make_uint2(
        pack_bf2((t[0]-mu)*inv, (t[1]-mu)*inv),
        pack_bf2((t[2]-mu)*inv, (t[3]-mu)*inv));
}

// transpose fp32 [R,C] -> bf16 [C,R], optional per-input-row gain, batched via z
__global__ void trans_bf16_k(const float* __restrict__ in,
                             __nv_bfloat16* __restrict__ oh, int R, int C,
                             const float* __restrict__ gain) {
    __shared__ float s[32][36];
    size_t bz = (size_t)blockIdx.z * R * C;
    int c0 = blockIdx.x * 32, r0 = blockIdx.y * 32;
    int t = threadIdx.x;
    {
        int r = t >> 3, c4 = (t & 7) * 4;
        float4 v = *(const float4*)(in + bz + (size_t)(r0 + r)*C + c0 + c4);
        if (gain) {
            float gv = gain[r0 + r];
            v.x *= gv; v.y *= gv; v.z *= gv; v.w *= gv;
        }
        *(float4*)&s[r][c4] = v;
    }
    __syncthreads();
    {
        int c = t & 31, rg = (t >> 5) * 4;
        uint32_t h01 = pack_bf2(s[rg][c],   s[rg+1][c]);
        uint32_t h23 = pack_bf2(s[rg+2][c], s[rg+3][c]);
        size_t o = bz + (size_t)(c0 + c)*R + r0 + rg;
        *(uint2*)(oh + o) = make_uint2(h01, h23);
    }
}

// depthwise conv K=17 + residual, bf16 in/out (C=2048), float4 smem compute,
// fused group-transpose -> ht
__global__ void dwconv_bf16_k(const __nv_bfloat16* __restrict__ h, const float* __restrict__ dw,
                              __nv_bfloat16* __restrict__ out, __nv_bfloat16* __restrict__ ht) {
    const int C = HIDc, CT4 = 16, NTile = 128, HALO = 8;
    __shared__ float4 sh[NTile + 2*HALO][CT4];
    __shared__ float4 sdw[KK][CT4];
    int b = blockIdx.z, n0 = blockIdx.y * NTile, c0 = blockIdx.x * 64;  // 64 channels
    // load: 144 rows x 8 uint4 (8 bf16 each -> 2 float4 slots)
    for (int idx = threadIdx.x; idx < 144*8; idx += 256) {
        int r = idx >> 3, q = idx & 7;
        int n = n0 - HALO + r;
        float4 f0, f1;
        if (n >= 0 && n < Nn) {
            uint4 uv = *(const uint4*)(h + ((size_t)b*Nn + n)*C + c0 + q*8);
            float tmp[4];
            unpk4(make_uint2(uv.x, uv.y), tmp);
            f0 = make_float4(tmp[0], tmp[1], tmp[2], tmp[3]);
            unpk4(make_uint2(uv.z, uv.w), tmp);
            f1 = make_float4(tmp[0], tmp[1], tmp[2], tmp[3]);
        } else {
            f0 = make_float4(0,0,0,0); f1 = f0;
        }
        sh[r][q*2]   = f0;
        sh[r][q*2+1] = f1;
    }
    for (int idx = threadIdx.x; idx < KK*CT4; idx += 256) {
        int k = idx >> 4, c = idx & 15;
        const float* w = dw + k*C + c0 + c*4;
        sdw[k][c] = make_float4(w[0], w[1], w[2], w[3]);
    }
    __syncthreads();
    float4 accs[8];
    #pragma unroll
    for (int e = 0; e < 8; e++) {
        int idx = threadIdx.x + e*256;          // 128 rows x 16 float4 slots
        int r = idx >> 4, c = idx & 15;
        float4 acc = sh[r + HALO][c];
        #pragma unroll
        for (int k = 0; k < KK; k++) {
            float4 a = sh[r + k][c], w = sdw[k][c];
            acc.x += a.x*w.x; acc.y += a.y*w.y; acc.z += a.z*w.z; acc.w += a.w*w.w;
        }
        accs[e] = acc;
        *(uint2*)(out + ((size_t)b*Nn + n0 + r)*C + c0 + c*4) =
            make_uint2(pack_bf2(acc.x, acc.y), pack_bf2(acc.z, acc.w));
    }
    // stage for group-transpose: padded f32 [128][65]
    __syncthreads();
    float* sout = (float*)sh;
    #pragma unroll
    for (int e = 0; e < 8; e++) {
        int idx = threadIdx.x + e*256;
        int r = idx >> 4, c = idx & 15;
        float* p = &sout[r*65 + c*4];
        p[0] = accs[e].x; p[1] = accs[e].y; p[2] = accs[e].z; p[3] = accs[e].w;
    }
    __syncthreads();
    int g = n0 >> 8, nloc = n0 & 255;
    size_t basebg = ((size_t)(b*Gg + g)*C + c0) * 256 + nloc;
    #pragma unroll
    for (int e = 0; e < 8; e++) {
        int idx = threadIdx.x + e*256;          // 64 ch x 32 quad-rows
        int cc = idx >> 5, r4 = (idx & 31) * 4;
        float v0 = sout[(r4+0)*65 + cc];
        float v1 = sout[(r4+1)*65 + cc];
        float v2 = sout[(r4+2)*65 + cc];
        float v3 = sout[(r4+3)*65 + cc];
        *(uint2*)(ht + basebg + (size_t)cc*256 + r4) =
            make_uint2(pack_bf2(v0, v1), pack_bf2(v2, v3));
    }
}

// f32 depthwise conv K=17 + residual (+ extra residual) — final path
__global__ void dwconv4_k(const float4* __restrict__ h4, const float* __restrict__ dw,
                          const float4* __restrict__ extra4, float4* __restrict__ out4, int C) {
    const int CT4 = 16, NTile = 128, HALO = 8;
    __shared__ float4 sh[NTile + 2*HALO][CT4];
    __shared__ float4 sdw[KK][CT4];
    int b = blockIdx.z, n0 = blockIdx.y * NTile, c0 = blockIdx.x * CT4;
    int C4 = C >> 2;
    const float4* base = h4 + (size_t)b*Nn*C4 + c0;
    for (int idx = threadIdx.x; idx < (NTile + 2*HALO)*CT4; idx += blockDim.x) {
        int r = idx >> 4, c = idx & 15;
        int n = n0 - HALO + r;
        sh[r][c] = (n >= 0 && n < Nn) ? base[(size_t)n*C4 + c] : make_float4(0,0,0,0);
    }
    for (int idx = threadIdx.x; idx < KK*CT4; idx += blockDim.x) {
        int k = idx >> 4, c = idx & 15;
        const float* w = dw + k*C + (c0 + c)*4;
        sdw[k][c] = make_float4(w[0], w[1], w[2], w[3]);
    }
    __syncthreads();
    for (int idx = threadIdx.x; idx < NTile*CT4; idx += blockDim.x) {
        int r = idx >> 4, c = idx & 15;
        float4 acc = sh[r + HALO][c];
        #pragma unroll
        for (int k = 0; k < KK; k++) {
            float4 a = sh[r + k][c], w = sdw[k][c];
            acc.x += a.x*w.x; acc.y += a.y*w.y; acc.z += a.z*w.z; acc.w += a.w*w.w;
        }
        size_t o = (size_t)b*Nn*C4 + (size_t)(n0 + r)*C4 + c0 + c;
        if (extra4) {
            float4 ev = extra4[o];
            acc.x += ev.x; acc.y += ev.y; acc.z += ev.z; acc.w += ev.w;
        }
        out4[o] = acc;
    }
}

// dwconv (C=128) + residual, fused offset-scale split epilogue
__global__ void dwconv_qsplit_k(const float4* __restrict__ h4, const float* __restrict__ dw,
                                const float* __restrict__ gamma, const float* __restrict__ beta,
                                __nv_bfloat16* __restrict__ qqh, __nv_bfloat16* __restrict__ lqh,
                                __nv_bfloat16* __restrict__ qkh, float* __restrict__ lkf) {
    const int CT4 = 16, NTile = 128, HALO = 8, C4 = 32;
    __shared__ float4 sh[NTile + 2*HALO][CT4];
    __shared__ float4 sdw[KK][CT4];
    __shared__ float sg[4][64], sb[4][64];
    int b = blockIdx.z, n0 = blockIdx.y * NTile, c0 = blockIdx.x * CT4;
    const float4* base = h4 + (size_t)b*Nn*C4 + c0;
    for (int idx = threadIdx.x; idx < (NTile + 2*HALO)*CT4; idx += blockDim.x) {
        int r = idx >> 4, c = idx & 15;
        int n = n0 - HALO + r;
        sh[r][c] = (n >= 0 && n < Nn) ? base[(size_t)n*C4 + c] : make_float4(0,0,0,0);
    }
    for (int idx = threadIdx.x; idx < KK*CT4; idx += blockDim.x) {
        int k = idx >> 4, c = idx & 15;
        const float* w = dw + k*DQK + (c0 + c)*4;
        sdw[k][c] = make_float4(w[0], w[1], w[2], w[3]);
    }
    {
        int s = threadIdx.x >> 6, j = threadIdx.x & 63;
        sg[s][j] = gamma[s*DQK + c0*4 + j];
        sb[s][j] = beta [s*DQK + c0*4 + j];
    }
    __syncthreads();
    #pragma unroll
    for (int e = 0; e < 8; e++) {
        int idx = threadIdx.x + e*256;
        int r = idx >> 4, c = idx & 15;
        float4 acc = sh[r + HALO][c];
        #pragma unroll
        for (int k = 0; k < KK; k++) {
            float4 a = sh[r + k][c], w = sdw[k][c];
            acc.x += a.x*w.x; acc.y += a.y*w.y; acc.z += a.z*w.z; acc.w += a.w*w.w;
        }
        float av[4] = {acc.x, acc.y, acc.z, acc.w};
        int chl = c*4;
        float q[4], lq[4], qk[4], lk[4];
        #pragma unroll
        for (int j = 0; j < 4; j++) {
            q[j]  = av[j]*sg[0][chl+j] + sb[0][chl+j];
            lq[j] = av[j]*sg[1][chl+j] + sb[1][chl+j];
            qk[j] = av[j]*sg[2][chl+j] + sb[2][chl+j];
            lk[j] = av[j]*sg[3][chl+j] + sb[3][chl+j];
        }
        size_t ob = ((size_t)b*Nn + n0 + r)*DQK + (c0 + c)*4;
        *(uint2*)(qqh + ob) = make_uint2(pack_bf2(q[0],q[1]),  pack_bf2(q[2],q[3]));
        *(uint2*)(lqh + ob) = make_uint2(pack_bf2(lq[0],lq[1]), pack_bf2(lq[2],lq[3]));
        *(uint2*)(qkh + ob) = make_uint2(pack_bf2(qk[0],qk[1]), pack_bf2(qk[2],qk[3]));
        *(float4*)(lkf + ob) = make_float4(lk[0], lk[1], lk[2], lk[3]);
    }
}

__global__ void cumsum_bf16_k(const float* __restrict__ kvf,
                              __nv_bfloat16* __restrict__ oh) {
    const size_t S = (size_t)2048*128;
    long i2 = (long)blockIdx.x * blockDim.x + threadIdx.x;
    if (i2 >= (long)Bb*(S/2)) return;
    size_t b = (size_t)i2 / (S/2), r2 = (size_t)i2 % (S/2);
    size_t base2 = b*Gg*(S/2) + r2;
    float s0 = 0.f, s1 = 0.f;
    #pragma unroll
    for (int g = 0; g < Gg; g++) {
        size_t o2 = base2 + (size_t)g*(S/2);
        float2 v = ((const float2*)kvf)[o2];
        ((uint32_t*)oh)[o2] = pack_bf2(s0, s1);
        s0 += v.x; s1 += v.y;
    }
}

// ================= HMMA bf16 GEMM — two-part K, split-C, bf16-out option ========
#define LDA 72
#define STG_BYTES 36864
#define GSMEM (2*STG_BYTES)

__global__ void __launch_bounds__(256, 2) gemm_k(
    const __nv_bfloat16* __restrict__ A1, const __nv_bfloat16* __restrict__ B1,
    const __nv_bfloat16* __restrict__ A2, const __nv_bfloat16* __restrict__ B2,
    float* C, float* Cq, __nv_bfloat16* Ch,
    int M, int N, int K1, int K2, const float* __restrict__ bias, float alpha, int flags,
    long long sA1, long long sB1, long long sA2, long long sB2, long long sC)
{
    extern __shared__ __align__(16) unsigned char smem[];
    uint32_t sbase = smem_to_u32(smem);
    int tid = threadIdx.x, lane = tid & 31, wid = tid >> 5;
    int wm = wid & 3, wn = wid >> 2;
    int brow = blockIdx.y * 128, bcol = blockIdx.x * 128;
    long long bz = blockIdx.z;
    A1 += bz*sA1; B1 += bz*sB1;
    if (A2) { A2 += bz*sA2; B2 += bz*sB2; }
    if (C)  C  += bz*sC;
    if (Ch) Ch += bz*sC;

    if ((flags & F_SCORE) && bcol > brow) {
        uint4 z = make_uint4(0,0,0,0);
        for (int e = tid; e < 2048; e += 256) {
            int row = e >> 4, seg = e & 15;
            *(uint4*)(Ch + (size_t)(brow + row)*N + bcol + seg*8) = z;
        }
        return;
    }

    float acc[2][8][4];
    #pragma unroll
    for (int i = 0; i < 2; i++)
        #pragma unroll
        for (int j = 0; j < 8; j++)
            #pragma unroll
            for (int q = 0; q < 4; q++) acc[i][j][q] = 0.f;

    uint32_t aOff = (uint32_t)(((wm*32 + (lane & 15)) * LDA + (lane >> 4)*8) * 2);
    uint32_t bOff = (uint32_t)(((wn*64 + ((lane >> 4) & 1)*8 + (lane & 7)) * LDA
                                + ((lane >> 3) & 1)*8) * 2) + 18432;
    const int ldr = tid >> 3, lds2 = tid & 7;

    int KC1 = K1 >> 6;
    if (flags & F_TRIA) {
        int kc = (brow + 128) >> 6;
        if (kc < KC1) KC1 = kc;
    }
    const int KC2 = K2 >> 6;
    const int KC = KC1 + KC2;

    auto issue = [&](int it) {
        const __nv_bfloat16 *Ap, *Bp; int k0, Kst;
        if (it < KC1) { Ap = A1; Bp = B1; k0 = it << 6;          Kst = K1; }
        else          { Ap = A2; Bp = B2; k0 = (it - KC1) << 6;  Kst = K2; }
        uint32_t sa = sbase + (uint32_t)(it & 1)*STG_BYTES;
        #pragma unroll
        for (int e = 0; e < 4; e++) {
            int r = ldr + e*32;
            cp16(sa + (uint32_t)(r*144 + lds2*16),
                 Ap + (size_t)(brow + r)*Kst + k0 + lds2*8);
            cp16(sa + 18432u + (uint32_t)(r*144 + lds2*16),
                 Bp + (size_t)(bcol + r)*Kst + k0 + lds2*8);
        }
        CP_COMMIT();
    };

    issue(0);
    for (int it = 0; it < KC; ++it) {
        if (it + 1 < KC) { issue(it + 1); CP_WAIT(1); }
        else             { CP_WAIT(0); }
        __syncthreads();
        uint32_t stg = sbase + (uint32_t)(it & 1)*STG_BYTES;
        uint32_t aB = stg + aOff, bB = stg + bOff;
        #pragma unroll
        for (int kk = 0; kk < 4; kk++) {
            uint32_t af[2][4], bfr[4][4];
            #pragma unroll
            for (int i = 0; i < 2; i++)
                ldsm4(af[i], aB + (uint32_t)((i*16*LDA + kk*16) * 2));
            #pragma unroll
            for (int p = 0; p < 4; p++)
                ldsm4(bfr[p], bB + (uint32_t)((p*16*LDA + kk*16) * 2));
            #pragma unroll
            for (int i = 0; i < 2; i++)
                #pragma unroll
                for (int j = 0; j < 8; j++)
                    mma16816(acc[i][j], af[i], bfr[j>>1][(j&1)*2], bfr[j>>1][(j&1)*2+1]);
        }
        __syncthreads();
    }

    // ---- epilogue ----
    int g = lane >> 2, c2 = (lane & 3)*2;
    #pragma unroll
    for (int i = 0; i < 2; i++) {
        #pragma unroll
        for (int j = 0; j < 8; j++) {
            #pragma unroll
            for (int rr = 0; rr < 2; rr++) {
                int row = brow + wm*32 + i*16 + g + rr*8;
                int col = bcol + wn*64 + j*8 + c2;
                float v0 = acc[i][j][rr*2+0] * alpha;
                float v1 = acc[i][j][rr*2+1] * alpha;
                if (flags & F_SCORE) {
                    v0 = fmaxf(v0, 0.f); v0 *= v0;
                    v1 = fmaxf(v1, 0.f); v1 *= v1;
                    if (col     > row) v0 = 0.f;
                    if (col + 1 > row) v1 = 0.f;
                    *(uint32_t*)(Ch + (size_t)row*N + col) = pack_bf2(v0, v1);
                } else {
                    if (bias) { v0 += bias[col]; v1 += bias[col+1]; }
                    if (flags & F_SILU) {
                        v0 = v0 / (1.f + expf(-v0));
                        v1 = v1 / (1.f + expf(-v1));
                    }
                    if (Cq && col >= 2048) {
                        *(float2*)(Cq + (size_t)row*DQK + col - 2048) = make_float2(v0, v1);
                    } else if (flags & F_BF16) {
                        *(uint32_t*)(Ch + (size_t)row*N + col) = pack_bf2(v0, v1);
                    } else {
                        *(float2*)(C + (size_t)row*N + col) = make_float2(v0, v1);
                    }
                }
            }
        }
    }
}

// ================= launcher =================
extern "C" void kernel_launch(void* const* d_in, const int* in_sizes, int n_in,
                              void* d_out, int out_size) {
    const float* x      = (const float*)d_in[0];
    const float* ln_h_g = (const float*)d_in[1];
    const float* ln_h_b = (const float*)d_in[2];
    const float* W_h    = (const float*)d_in[3];
    const float* b_h    = (const float*)d_in[4];
    const float* dw_h   = (const float*)d_in[5];
    const float* ln_qk_g= (const float*)d_in[6];
    const float* ln_qk_b= (const float*)d_in[7];
    const float* W_qk   = (const float*)d_in[8];
    const float* b_qk   = (const float*)d_in[9];
    const float* dw_qk  = (const float*)d_in[10];
    const float* gamma  = (const float*)d_in[11];
    const float* beta   = (const float*)d_in[12];
    const float* ln_o_g = (const float*)d_in[13];
    const float* ln_o_b = (const float*)d_in[14];
    const float* W_o    = (const float*)d_in[15];
    const float* b_o    = (const float*)d_in[16];
    const float* dw_o   = (const float*)d_in[17];
    float* out = (float*)d_out;

    unsigned char* pool;
    cudaGetSymbolAddress((void**)&pool, g_pool);
    float*         opre = (float*)(pool + O_OPRE);
    __nv_bfloat16* lnH  = (__nv_bfloat16*)(pool + O_LNH);
    __nv_bfloat16* wCat = (__nv_bfloat16*)(pool + O_WCAT);
    __nv_bfloat16* woTH = (__nv_bfloat16*)(pool + O_WOTH);
    float*         bCat = (float*)(pool + O_BCAT);
    float*         bO   = (float*)(pool + O_BO);
    __nv_bfloat16* hB   = (__nv_bfloat16*)(pool + O_HB);
    __nv_bfloat16* hid  = (__nv_bfloat16*)(pool + O_HID);
    __nv_bfloat16* attB = (__nv_bfloat16*)(pool + O_ATT);
    __nv_bfloat16* hTH  = (__nv_bfloat16*)(pool + O_HTH);
    float*         qk   = (float*)(pool + O_QK);
    __nv_bfloat16* qqH  = (__nv_bfloat16*)(pool + O_QQH);
    __nv_bfloat16* lqH  = (__nv_bfloat16*)(pool + O_LQH);
    __nv_bfloat16* qkH  = (__nv_bfloat16*)(pool + O_QKH);
    float*         lkF  = (float*)(pool + O_LKF);
    __nv_bfloat16* lkTH = (__nv_bfloat16*)(pool + O_LKTH);
    __nv_bfloat16* attH = (__nv_bfloat16*)(pool + O_ATTH);
    float*         kvF  = (float*)(pool + O_KVF);
    __nv_bfloat16* kvH  = (__nv_bfloat16*)(pool + O_KVH);

    cudaFuncSetAttribute(gemm_k, cudaFuncAttributeMaxDynamicSharedMemorySize, GSMEM);

    // 1. weight transposes with LN-gain folding
    trans_bf16_k<<<dim3(2048/32, 512/32, 1), 256>>>(W_h,  wCat,            512, 2048, ln_h_g);
    trans_bf16_k<<<dim3(128/32,  512/32, 1), 256>>>(W_qk, wCat + 2048*512, 512, 128,  ln_qk_g);
    trans_bf16_k<<<dim3(512/32, 1024/32, 1), 256>>>(W_o,  woTH,            1024, 512, ln_o_g);
    // 2. effective biases
    bias_fold_k<<<2048, 256>>>(W_h,  ln_h_b,  b_h,  bCat,        512, 2048);
    bias_fold_k<<<128,  256>>>(W_qk, ln_qk_b, b_qk, bCat + 2048, 512, 128);
    bias_fold_k<<<512,  256>>>(W_o,  ln_o_b,  b_o,  bO,          1024, 512);
    // 3. fused shift + pure-xhat LN -> lnH
    ln_shift_k<<<NT, 256>>>(x, lnH);
    // 4. MERGED GEMM1+GEMM2 -> hB (bf16) / qk (f32), SiLU
    gemm_k<<<dim3(17, 128, 1), 256, GSMEM>>>(lnH, wCat, nullptr, nullptr, nullptr, qk, hB,
        NT, HIDc, Dd, 0, bCat, 1.f, F_SILU | F_BF16, 0, 0, 0, 0, 0);
    // 5. dwconv (bf16, float4 compute) -> hid, fused group-transpose -> hTH
    dwconv_bf16_k<<<dim3(32, 16, Bb), 256>>>(hB, dw_h, hid, hTH);
    // 6. dwconv(C=128) + fused offset-scale split
    dwconv_qsplit_k<<<dim3(2, 16, Bb), 256>>>((const float4*)qk, dw_qk, gamma, beta,
                                              qqH, lqH, qkH, lkF);
    // 7. lin_k per-group transpose -> lkT [bg,128,256]
    trans_bf16_k<<<dim3(4, 8, 64), 256>>>(lkF, lkTH, 256, 128, nullptr);
    // 8. scores -> attH (relu^2 causal)
    gemm_k<<<dim3(2, 2, 64), 256, GSMEM>>>(qqH, qkH, nullptr, nullptr, nullptr, nullptr, attH,
        GRP, GRP, DQK, 0, nullptr, 1.f/GRP, F_SCORE,
        (long long)GRP*DQK, (long long)GRP*DQK, 0, 0, (long long)GRP*GRP);
    // 9. lin kv (coalesced)
    gemm_k<<<dim3(1, 16, 64), 256, GSMEM>>>(hTH, lkTH, nullptr, nullptr, kvF, nullptr, nullptr,
        HIDc, DQK, GRP, 0, nullptr, 1.f/GRP, 0,
        (long long)HIDc*GRP, (long long)DQK*GRP, 0, 0, (long long)HIDc*DQK);
    // 10. exclusive group cumsum -> kvH
    cumsum_bf16_k<<<(int)(((size_t)Bb*2048*64 + 255)/256), 256>>>(kvF, kvH);
    // 11. MERGED quad-out + lin-out -> attB (bf16)
    gemm_k<<<dim3(16, 2, 64), 256, GSMEM>>>(attH, hTH, lqH, kvH, nullptr, nullptr, attB,
        GRP, HIDc, GRP, DQK, nullptr, 1.f, F_TRIA | F_BF16,
        (long long)GRP*GRP, (long long)HIDc*GRP,
        (long long)GRP*DQK, (long long)HIDc*DQK, (long long)GRP*HIDc);
    // 12. fused gating (bf16 in) + pure-xhat LN_o -> lnH
    gate_ln_k<<<NT, 256>>>(attB, hid, lnH);
    // 13. GEMM3 -> opre (f32, SiLU, folded gains/bias)
    gemm_k<<<dim3(4, 128, 1), 256, GSMEM>>>(lnH, woTH, nullptr, nullptr, opre, nullptr, nullptr,
        NT, Dd, 2*Dd, 0, bO, 1.f, F_SILU, 0, 0, 0, 0, 0);
    // 14. dwconv + x residual -> out (f32)
    dwconv4_k<<<dim3(8, 16, Bb), 256>>>((const float4*)opre, dw_o, (const float4*)x,
                                        (float4*)out, Dd);
}

// round 16
// speedup vs baseline: 1.1360x; 1.0001x over previous
#include <cuda_runtime.h>
#include <cuda_bf16.h>
#include <cstdint>

#define Bb    8
#define Nn    2048
#define Dd    512
#define HIDc  2048
#define DQK   128
#define GRP   256
#define Gg    8
#define NT    (Bb*Nn)
#define Ee    1024
#define KK    17

// ================= warp MMA / async helpers =================
__device__ __forceinline__ uint32_t smem_to_u32(const void* p) {
    uint32_t a;
    asm("{ .reg .u64 t; cvta.to.shared.u64 t, %1; cvt.u32.u64 %0, t; }" : "=r"(a) : "l"(p));
    return a;
}
__device__ __forceinline__ void ldsm4(uint32_t* r, uint32_t addr) {
    asm volatile("ldmatrix.sync.aligned.m8n8.x4.shared.b16 {%0,%1,%2,%3}, [%4];"
        : "=r"(r[0]), "=r"(r[1]), "=r"(r[2]), "=r"(r[3]) : "r"(addr));
}
__device__ __forceinline__ void mma16816(float* c, const uint32_t* a, uint32_t b0, uint32_t b1) {
    asm volatile(
        "mma.sync.aligned.m16n8k16.row.col.f32.bf16.bf16.f32 "
        "{%0,%1,%2,%3}, {%4,%5,%6,%7}, {%8,%9}, {%0,%1,%2,%3};"
        : "+f"(c[0]), "+f"(c[1]), "+f"(c[2]), "+f"(c[3])
        : "r"(a[0]), "r"(a[1]), "r"(a[2]), "r"(a[3]), "r"(b0), "r"(b1));
}
__device__ __forceinline__ void cp16(uint32_t dst, const void* src) {
    asm volatile("cp.async.cg.shared.global [%0], [%1], 16;" :: "r"(dst), "l"(src));
}
#define CP_COMMIT() asm volatile("cp.async.commit_group;" ::: "memory")
#define CP_WAIT(N)  asm volatile("cp.async.wait_group %0;" :: "n"(N) : "memory")

#define F_SILU  1
#define F_SCORE 4
#define F_TRIA  16
#define F_BF16  32

// ================= scratch pool =================
#define SZF(n) ((size_t)(n)*4)
#define SZB(n) ((size_t)(n)*2)
static constexpr size_t O_OPRE = 0;                                 // f32 [NT,512]
static constexpr size_t O_LNH  = O_OPRE + SZF((size_t)NT*512);      // bf16 [NT,1024]
static constexpr size_t O_WCAT = O_LNH  + SZB((size_t)NT*1024);     // bf16 [2176,512]
static constexpr size_t O_WOTH = O_WCAT + SZB(2176*512);            // bf16 [512,1024]
static constexpr size_t O_BCAT = O_WOTH + SZB(512*1024);            // f32 [2176]
static constexpr size_t O_BO   = O_BCAT + SZF(2176);                // f32 [512]
static constexpr size_t O_HB   = O_BO   + SZF(512);                 // bf16 [NT,2048] (h)
static constexpr size_t O_HID  = O_HB   + SZB((size_t)NT*2048);     // bf16 [NT,2048]
static constexpr size_t O_ATT  = O_HID  + SZB((size_t)NT*2048);     // bf16 [NT,2048]
static constexpr size_t O_HTH  = O_ATT  + SZB((size_t)NT*2048);     // bf16 [bg,2048,256]
static constexpr size_t O_QK   = O_HTH  + SZB((size_t)NT*2048);     // f32 [NT,128]
static constexpr size_t O_QQH  = O_QK   + SZF((size_t)NT*128);      // bf16 [NT,128] x3
static constexpr size_t O_LQH  = O_QQH  + SZB((size_t)NT*128);
static constexpr size_t O_QKH  = O_LQH  + SZB((size_t)NT*128);
static constexpr size_t O_LKF  = O_QKH  + SZB((size_t)NT*128);      // f32 [NT,128]
static constexpr size_t O_LKTH = O_LKF  + SZF((size_t)NT*128);      // bf16 [bg,128,256]
static constexpr size_t O_ATTH = O_LKTH + SZB((size_t)NT*128);      // bf16 [bg,256,256]
static constexpr size_t O_KVB  = O_ATTH + SZB((size_t)64*256*256);  // bf16 [bg,2048,128]
static constexpr size_t O_END  = O_KVB  + SZB((size_t)64*2048*128);
__device__ __align__(1024) unsigned char g_pool[O_END];

__device__ __forceinline__ uint32_t pack_bf2(float v0, float v1) {
    __nv_bfloat16 h0 = __float2bfloat16(v0), h1 = __float2bfloat16(v1);
    return ((uint32_t)__bfloat16_as_ushort(h1) << 16) | __bfloat16_as_ushort(h0);
}
__device__ __forceinline__ void unpk4(uint2 u, float* f) {
    f[0] = __bfloat162float(__ushort_as_bfloat16((unsigned short)(u.x & 0xffff)));
    f[1] = __bfloat162float(__ushort_as_bfloat16((unsigned short)(u.x >> 16)));
    f[2] = __bfloat162float(__ushort_as_bfloat16((unsigned short)(u.y & 0xffff)));
    f[3] = __bfloat162float(__ushort_as_bfloat16((unsigned short)(u.y >> 16)));
}

// ================= prep kernels =================
// merged effective-bias GEMV: blocks 0..2047 -> W_h, 2048..2175 -> W_qk, 2176..2687 -> W_o
__global__ void bias_fold_all_k(const float* __restrict__ W_h,  const float* __restrict__ lnb_h,
                                const float* __restrict__ b_h,
                                const float* __restrict__ W_qk, const float* __restrict__ lnb_qk,
                                const float* __restrict__ b_qk,
                                const float* __restrict__ W_o,  const float* __restrict__ lnb_o,
                                const float* __restrict__ b_o,
                                float* __restrict__ bCat, float* __restrict__ bO) {
    int blk = blockIdx.x;
    const float *W, *lnb, *bias; float* out; int K, N, n;
    if (blk < 2048)      { W = W_h;  lnb = lnb_h;  bias = b_h;  out = bCat;        K = 512;  N = 2048; n = blk; }
    else if (blk < 2176) { W = W_qk; lnb = lnb_qk; bias = b_qk; out = bCat + 2048; K = 512;  N = 128;  n = blk - 2048; }
    else                 { W = W_o;  lnb = lnb_o;  bias = b_o;  out = bO;          K = 1024; N = 512;  n = blk - 2176; }
    float s = 0.f;
    for (int k = threadIdx.x; k < K; k += blockDim.x)
        s += lnb[k] * W[(size_t)k*N + n];
    #pragma unroll
    for (int o = 16; o; o >>= 1) s += __shfl_xor_sync(~0u, s, o);
    __shared__ float sh[8];
    int w = threadIdx.x >> 5, l = threadIdx.x & 31;
    if (l == 0) sh[w] = s;
    __syncthreads();
    if (threadIdx.x == 0) {
        float ts = bias[n];
        for (int i = 0; i < (int)(blockDim.x >> 5); i++) ts += sh[i];
        out[n] = ts;
    }
}

// fused token-shift + pure-xhat LN (C=512) -> bf16
__global__ void ln_shift_k(const float* __restrict__ x, __nv_bfloat16* __restrict__ oh) {
    long t = blockIdx.x;
    int n = (int)(t % Nn);
    int i = threadIdx.x;
    const float2* xr = (const float2*)(x + t*Dd);
    const float2* xp = (const float2*)(x + (t-1)*Dd);
    float2 v;
    if (i < 128) v = (n == 0) ? make_float2(0.f, 0.f) : xp[i];
    else         v = xr[i];
    float s = v.x + v.y, s2 = v.x*v.x + v.y*v.y;
    #pragma unroll
    for (int o = 16; o; o >>= 1) {
        s  += __shfl_xor_sync(~0u, s,  o);
        s2 += __shfl_xor_sync(~0u, s2, o);
    }
    __shared__ float shs[8], shs2[8], smu, sinv;
    int w = i >> 5, l = i & 31;
    if (l == 0) { shs[w] = s; shs2[w] = s2; }
    __syncthreads();
    if (i == 0) {
        float ts = 0.f, ts2 = 0.f;
        for (int k = 0; k < 8; k++) { ts += shs[k]; ts2 += shs2[k]; }
        float mu = ts / Dd;
        smu = mu; sinv = rsqrtf(ts2 / Dd - mu*mu + 1e-5f);
    }
    __syncthreads();
    float mu = smu, inv = sinv;
    ((uint32_t*)(oh + t*Dd))[i] = pack_bf2((v.x - mu)*inv, (v.y - mu)*inv);
}

// fused gating + pure-xhat LN(1024), bf16 in -> bf16 out
__global__ void gate_ln_k(const __nv_bfloat16* __restrict__ att,
                          const __nv_bfloat16* __restrict__ hid,
                          __nv_bfloat16* __restrict__ oh) {
    long row = blockIdx.x;
    int i = threadIdx.x;
    float av[4], au[4], v[4], u[4], t[4];
    unpk4(((const uint2*)(att + row*HIDc))[i],      av);
    unpk4(((const uint2*)(att + row*HIDc + Ee))[i], au);
    unpk4(((const uint2*)(hid + row*HIDc))[i],      v);
    unpk4(((const uint2*)(hid + row*HIDc + Ee))[i], u);
    float s = 0.f, s2 = 0.f;
    #pragma unroll
    for (int j = 0; j < 4; j++) {
        t[j] = au[j] * v[j] * (1.f / (1.f + expf(-(av[j] * u[j]))));
        s += t[j]; s2 += t[j]*t[j];
    }
    #pragma unroll
    for (int o = 16; o; o >>= 1) {
        s  += __shfl_xor_sync(~0u, s,  o);
        s2 += __shfl_xor_sync(~0u, s2, o);
    }
    __shared__ float shs[8], shs2[8], smu, sinv;
    int w = i >> 5, l = i & 31;
    if (l == 0) { shs[w] = s; shs2[w] = s2; }
    __syncthreads();
    if (i == 0) {
        float ts = 0.f, ts2 = 0.f;
        for (int k = 0; k < 8; k++) { ts += shs[k]; ts2 += shs2[k]; }
        float mu = ts / 1024.f;
        smu = mu; sinv = rsqrtf(ts2 / 1024.f - mu*mu + 1e-5f);
    }
    __syncthreads();
    float mu = smu, inv = sinv;
    ((uint2*)(oh + row*1024))[i] = make_uint2(
        pack_bf2((t[0]-mu)*inv, (t[1]-mu)*inv),
        pack_bf2((t[2]-mu)*inv, (t[3]-mu)*inv));
}

// transpose fp32 [R,C] -> bf16 [C,R], optional per-input-row gain, batched via z
__global__ void trans_bf16_k(const float* __restrict__ in,
                             __nv_bfloat16* __restrict__ oh, int R, int C,
                             const float* __restrict__ gain) {
    __shared__ float s[32][36];
    size_t bz = (size_t)blockIdx.z * R * C;
    int c0 = blockIdx.x * 32, r0 = blockIdx.y * 32;
    int t = threadIdx.x;
    {
        int r = t >> 3, c4 = (t & 7) * 4;
        float4 v = *(const float4*)(in + bz + (size_t)(r0 + r)*C + c0 + c4);
        if (gain) {
            float gv = gain[r0 + r];
            v.x *= gv; v.y *= gv; v.z *= gv; v.w *= gv;
        }
        *(float4*)&s[r][c4] = v;
    }
    __syncthreads();
    {
        int c = t & 31, rg = (t >> 5) * 4;
        uint32_t h01 = pack_bf2(s[rg][c],   s[rg+1][c]);
        uint32_t h23 = pack_bf2(s[rg+2][c], s[rg+3][c]);
        size_t o = bz + (size_t)(c0 + c)*R + r0 + rg;
        *(uint2*)(oh + o) = make_uint2(h01, h23);
    }
}

// depthwise conv K=17 + residual, bf16 in/out (C=2048), float4 smem compute,
// fused group-transpose -> ht
__global__ void dwconv_bf16_k(const __nv_bfloat16* __restrict__ h, const float* __restrict__ dw,
                              __nv_bfloat16* __restrict__ out, __nv_bfloat16* __restrict__ ht) {
    const int C = HIDc, CT4 = 16, NTile = 128, HALO = 8;
    __shared__ float4 sh[NTile + 2*HALO][CT4];
    __shared__ float4 sdw[KK][CT4];
    int b = blockIdx.z, n0 = blockIdx.y * NTile, c0 = blockIdx.x * 64;
    for (int idx = threadIdx.x; idx < 144*8; idx += 256) {
        int r = idx >> 3, q = idx & 7;
        int n = n0 - HALO + r;
        float4 f0, f1;
        if (n >= 0 && n < Nn) {
            uint4 uv = *(const uint4*)(h + ((size_t)b*Nn + n)*C + c0 + q*8);
            float tmp[4];
            unpk4(make_uint2(uv.x, uv.y), tmp);
            f0 = make_float4(tmp[0], tmp[1], tmp[2], tmp[3]);
            unpk4(make_uint2(uv.z, uv.w), tmp);
            f1 = make_float4(tmp[0], tmp[1], tmp[2], tmp[3]);
        } else {
            f0 = make_float4(0,0,0,0); f1 = f0;
        }
        sh[r][q*2]   = f0;
        sh[r][q*2+1] = f1;
    }
    for (int idx = threadIdx.x; idx < KK*CT4; idx += 256) {
        int k = idx >> 4, c = idx & 15;
        const float* w = dw + k*C + c0 + c*4;
        sdw[k][c] = make_float4(w[0], w[1], w[2], w[3]);
    }
    __syncthreads();
    float4 accs[8];
    #pragma unroll
    for (int e = 0; e < 8; e++) {
        int idx = threadIdx.x + e*256;
        int r = idx >> 4, c = idx & 15;
        float4 acc = sh[r + HALO][c];
        #pragma unroll
        for (int k = 0; k < KK; k++) {
            float4 a = sh[r + k][c], w = sdw[k][c];
            acc.x += a.x*w.x; acc.y += a.y*w.y; acc.z += a.z*w.z; acc.w += a.w*w.w;
        }
        accs[e] = acc;
        *(uint2*)(out + ((size_t)b*Nn + n0 + r)*C + c0 + c*4) =
            make_uint2(pack_bf2(acc.x, acc.y), pack_bf2(acc.z, acc.w));
    }
    __syncthreads();
    float* sout = (float*)sh;
    #pragma unroll
    for (int e = 0; e < 8; e++) {
        int idx = threadIdx.x + e*256;
        int r = idx >> 4, c = idx & 15;
        float* p = &sout[r*65 + c*4];
        p[0] = accs[e].x; p[1] = accs[e].y; p[2] = accs[e].z; p[3] = accs[e].w;
    }
    __syncthreads();
    int g = n0 >> 8, nloc = n0 & 255;
    size_t basebg = ((size_t)(b*Gg + g)*C + c0) * 256 + nloc;
    #pragma unroll
    for (int e = 0; e < 8; e++) {
        int idx = threadIdx.x + e*256;
        int cc = idx >> 5, r4 = (idx & 31) * 4;
        float v0 = sout[(r4+0)*65 + cc];
        float v1 = sout[(r4+1)*65 + cc];
        float v2 = sout[(r4+2)*65 + cc];
        float v3 = sout[(r4+3)*65 + cc];
        *(uint2*)(ht + basebg + (size_t)cc*256 + r4) =
            make_uint2(pack_bf2(v0, v1), pack_bf2(v2, v3));
    }
}

// f32 depthwise conv K=17 + residual (+ extra residual) — final path
__global__ void dwconv4_k(const float4* __restrict__ h4, const float* __restrict__ dw,
                          const float4* __restrict__ extra4, float4* __restrict__ out4, int C) {
    const int CT4 = 16, NTile = 128, HALO = 8;
    __shared__ float4 sh[NTile + 2*HALO][CT4];
    __shared__ float4 sdw[KK][CT4];
    int b = blockIdx.z, n0 = blockIdx.y * NTile, c0 = blockIdx.x * CT4;
    int C4 = C >> 2;
    const float4* base = h4 + (size_t)b*Nn*C4 + c0;
    for (int idx = threadIdx.x; idx < (NTile + 2*HALO)*CT4; idx += blockDim.x) {
        int r = idx >> 4, c = idx & 15;
        int n = n0 - HALO + r;
        sh[r][c] = (n >= 0 && n < Nn) ? base[(size_t)n*C4 + c] : make_float4(0,0,0,0);
    }
    for (int idx = threadIdx.x; idx < KK*CT4; idx += blockDim.x) {
        int k = idx >> 4, c = idx & 15;
        const float* w = dw + k*C + (c0 + c)*4;
        sdw[k][c] = make_float4(w[0], w[1], w[2], w[3]);
    }
    __syncthreads();
    for (int idx = threadIdx.x; idx < NTile*CT4; idx += blockDim.x) {
        int r = idx >> 4, c = idx & 15;
        float4 acc = sh[r + HALO][c];
        #pragma unroll
        for (int k = 0; k < KK; k++) {
            float4 a = sh[r + k][c], w = sdw[k][c];
            acc.x += a.x*w.x; acc.y += a.y*w.y; acc.z += a.z*w.z; acc.w += a.w*w.w;
        }
        size_t o = (size_t)b*Nn*C4 + (size_t)(n0 + r)*C4 + c0 + c;
        if (extra4) {
            float4 ev = extra4[o];
            acc.x += ev.x; acc.y += ev.y; acc.z += ev.z; acc.w += ev.w;
        }
        out4[o] = acc;
    }
}

// dwconv (C=128) + residual, fused offset-scale split epilogue
__global__ void dwconv_qsplit_k(const float4* __restrict__ h4, const float* __restrict__ dw,
                                const float* __restrict__ gamma, const float* __restrict__ beta,
                                __nv_bfloat16* __restrict__ qqh, __nv_bfloat16* __restrict__ lqh,
                                __nv_bfloat16* __restrict__ qkh, float* __restrict__ lkf) {
    const int CT4 = 16, NTile = 128, HALO = 8, C4 = 32;
    __shared__ float4 sh[NTile + 2*HALO][CT4];
    __shared__ float4 sdw[KK][CT4];
    __shared__ float sg[4][64], sb[4][64];
    int b = blockIdx.z, n0 = blockIdx.y * NTile, c0 = blockIdx.x * CT4;
    const float4* base = h4 + (size_t)b*Nn*C4 + c0;
    for (int idx = threadIdx.x; idx < (NTile + 2*HALO)*CT4; idx += blockDim.x) {
        int r = idx >> 4, c = idx & 15;
        int n = n0 - HALO + r;
        sh[r][c] = (n >= 0 && n < Nn) ? base[(size_t)n*C4 + c] : make_float4(0,0,0,0);
    }
    for (int idx = threadIdx.x; idx < KK*CT4; idx += blockDim.x) {
        int k = idx >> 4, c = idx & 15;
        const float* w = dw + k*DQK + (c0 + c)*4;
        sdw[k][c] = make_float4(w[0], w[1], w[2], w[3]);
    }
    {
        int s = threadIdx.x >> 6, j = threadIdx.x & 63;
        sg[s][j] = gamma[s*DQK + c0*4 + j];
        sb[s][j] = beta [s*DQK + c0*4 + j];
    }
    __syncthreads();
    #pragma unroll
    for (int e = 0; e < 8; e++) {
        int idx = threadIdx.x + e*256;
        int r = idx >> 4, c = idx & 15;
        float4 acc = sh[r + HALO][c];
        #pragma unroll
        for (int k = 0; k < KK; k++) {
            float4 a = sh[r + k][c], w = sdw[k][c];
            acc.x += a.x*w.x; acc.y += a.y*w.y; acc.z += a.z*w.z; acc.w += a.w*w.w;
        }
        float av[4] = {acc.x, acc.y, acc.z, acc.w};
        int chl = c*4;
        float q[4], lq[4], qk[4], lk[4];
        #pragma unroll
        for (int j = 0; j < 4; j++) {
            q[j]  = av[j]*sg[0][chl+j] + sb[0][chl+j];
            lq[j] = av[j]*sg[1][chl+j] + sb[1][chl+j];
            qk[j] = av[j]*sg[2][chl+j] + sb[2][chl+j];
            lk[j] = av[j]*sg[3][chl+j] + sb[3][chl+j];
        }
        size_t ob = ((size_t)b*Nn + n0 + r)*DQK + (c0 + c)*4;
        *(uint2*)(qqh + ob) = make_uint2(pack_bf2(q[0],q[1]),  pack_bf2(q[2],q[3]));
        *(uint2*)(lqh + ob) = make_uint2(pack_bf2(lq[0],lq[1]), pack_bf2(lq[2],lq[3]));
        *(uint2*)(qkh + ob) = make_uint2(pack_bf2(qk[0],qk[1]), pack_bf2(qk[2],qk[3]));
        *(float4*)(lkf + ob) = make_float4(lk[0], lk[1], lk[2], lk[3]);
    }
}

// in-place exclusive group-cumsum over bf16 kv [b][g][2048*128]
__global__ void cumsum_bf16_k(__nv_bfloat16* kv) {
    const size_t S = (size_t)2048*128;
    long i2 = (long)blockIdx.x * blockDim.x + threadIdx.x;   // over Bb*S/2
    if (i2 >= (long)Bb*(S/2)) return;
    size_t b = (size_t)i2 / (S/2), r2 = (size_t)i2 % (S/2);
    size_t base2 = b*Gg*(S/2) + r2;
    float s0 = 0.f, s1 = 0.f;
    uint32_t* kv2 = (uint32_t*)kv;
    #pragma unroll
    for (int g = 0; g < Gg; g++) {
        size_t o2 = base2 + (size_t)g*(S/2);
        uint32_t uv = kv2[o2];
        float v0 = __bfloat162float(__ushort_as_bfloat16((unsigned short)(uv & 0xffff)));
        float v1 = __bfloat162float(__ushort_as_bfloat16((unsigned short)(uv >> 16)));
        kv2[o2] = pack_bf2(s0, s1);
        s0 += v0; s1 += v1;
    }
}

// ================= HMMA bf16 GEMM — two-part K, split-C, bf16-out option ========
#define LDA 72
#define STG_BYTES 36864
#define GSMEM (2*STG_BYTES)

__global__ void __launch_bounds__(256, 2) gemm_k(
    const __nv_bfloat16* __restrict__ A1, const __nv_bfloat16* __restrict__ B1,
    const __nv_bfloat16* __restrict__ A2, const __nv_bfloat16* __restrict__ B2,
    float* C, float* Cq, __nv_bfloat16* Ch,
    int M, int N, int K1, int K2, const float* __restrict__ bias, float alpha, int flags,
    long long sA1, long long sB1, long long sA2, long long sB2, long long sC)
{
    extern __shared__ __align__(16) unsigned char smem[];
    uint32_t sbase = smem_to_u32(smem);
    int tid = threadIdx.x, lane = tid & 31, wid = tid >> 5;
    int wm = wid & 3, wn = wid >> 2;
    int brow = blockIdx.y * 128, bcol = blockIdx.x * 128;
    long long bz = blockIdx.z;
    A1 += bz*sA1; B1 += bz*sB1;
    if (A2) { A2 += bz*sA2; B2 += bz*sB2; }
    if (C)  C  += bz*sC;
    if (Ch) Ch += bz*sC;

    if ((flags & F_SCORE) && bcol > brow) {
        uint4 z = make_uint4(0,0,0,0);
        for (int e = tid; e < 2048; e += 256) {
            int row = e >> 4, seg = e & 15;
            *(uint4*)(Ch + (size_t)(brow + row)*N + bcol + seg*8) = z;
        }
        return;
    }

    float acc[2][8][4];
    #pragma unroll
    for (int i = 0; i < 2; i++)
        #pragma unroll
        for (int j = 0; j < 8; j++)
            #pragma unroll
            for (int q = 0; q < 4; q++) acc[i][j][q] = 0.f;

    uint32_t aOff = (uint32_t)(((wm*32 + (lane & 15)) * LDA + (lane >> 4)*8) * 2);
    uint32_t bOff = (uint32_t)(((wn*64 + ((lane >> 4) & 1)*8 + (lane & 7)) * LDA
                                + ((lane >> 3) & 1)*8) * 2) + 18432;
    const int ldr = tid >> 3, lds2 = tid & 7;

    int KC1 = K1 >> 6;
    if (flags & F_TRIA) {
        int kc = (brow + 128) >> 6;
        if (kc < KC1) KC1 = kc;
    }
    const int KC2 = K2 >> 6;
    const int KC = KC1 + KC2;

    auto issue = [&](int it) {
        const __nv_bfloat16 *Ap, *Bp; int k0, Kst;
        if (it < KC1) { Ap = A1; Bp = B1; k0 = it << 6;          Kst = K1; }
        else          { Ap = A2; Bp = B2; k0 = (it - KC1) << 6;  Kst = K2; }
        uint32_t sa = sbase + (uint32_t)(it & 1)*STG_BYTES;
        #pragma unroll
        for (int e = 0; e < 4; e++) {
            int r = ldr + e*32;
            cp16(sa + (uint32_t)(r*144 + lds2*16),
                 Ap + (size_t)(brow + r)*Kst + k0 + lds2*8);
            cp16(sa + 18432u + (uint32_t)(r*144 + lds2*16),
                 Bp + (size_t)(bcol + r)*Kst + k0 + lds2*8);
        }
        CP_COMMIT();
    };

    issue(0);
    for (int it = 0; it < KC; ++it) {
        if (it + 1 < KC) { issue(it + 1); CP_WAIT(1); }
        else             { CP_WAIT(0); }
        __syncthreads();
        uint32_t stg = sbase + (uint32_t)(it & 1)*STG_BYTES;
        uint32_t aB = stg + aOff, bB = stg + bOff;
        #pragma unroll
        for (int kk = 0; kk < 4; kk++) {
            uint32_t af[2][4], bfr[4][4];
            #pragma unroll
            for (int i = 0; i < 2; i++)
                ldsm4(af[i], aB + (uint32_t)((i*16*LDA + kk*16) * 2));
            #pragma unroll
            for (int p = 0; p < 4; p++)
                ldsm4(bfr[p], bB + (uint32_t)((p*16*LDA + kk*16) * 2));
            #pragma unroll
            for (int i = 0; i < 2; i++)
                #pragma unroll
                for (int j = 0; j < 8; j++)
                    mma16816(acc[i][j], af[i], bfr[j>>1][(j&1)*2], bfr[j>>1][(j&1)*2+1]);
        }
        __syncthreads();
    }

    // ---- epilogue ----
    int g = lane >> 2, c2 = (lane & 3)*2;
    #pragma unroll
    for (int i = 0; i < 2; i++) {
        #pragma unroll
        for (int j = 0; j < 8; j++) {
            #pragma unroll
            for (int rr = 0; rr < 2; rr++) {
                int row = brow + wm*32 + i*16 + g + rr*8;
                int col = bcol + wn*64 + j*8 + c2;
                float v0 = acc[i][j][rr*2+0] * alpha;
                float v1 = acc[i][j][rr*2+1] * alpha;
                if (flags & F_SCORE) {
                    v0 = fmaxf(v0, 0.f); v0 *= v0;
                    v1 = fmaxf(v1, 0.f); v1 *= v1;
                    if (col     > row) v0 = 0.f;
                    if (col + 1 > row) v1 = 0.f;
                    *(uint32_t*)(Ch + (size_t)row*N + col) = pack_bf2(v0, v1);
                } else {
                    if (bias) { v0 += bias[col]; v1 += bias[col+1]; }
                    if (flags & F_SILU) {
                        v0 = v0 / (1.f + expf(-v0));
                        v1 = v1 / (1.f + expf(-v1));
                    }
                    if (Cq && col >= 2048) {
                        *(float2*)(Cq + (size_t)row*DQK + col - 2048) = make_float2(v0, v1);
                    } else if (flags & F_BF16) {
                        *(uint32_t*)(Ch + (size_t)row*N + col) = pack_bf2(v0, v1);
                    } else {
                        *(float2*)(C + (size_t)row*N + col) = make_float2(v0, v1);
                    }
                }
            }
        }
    }
}

// ================= launcher =================
extern "C" void kernel_launch(void* const* d_in, const int* in_sizes, int n_in,
                              void* d_out, int out_size) {
    const float* x      = (const float*)d_in[0];
    const float* ln_h_g = (const float*)d_in[1];
    const float* ln_h_b = (const float*)d_in[2];
    const float* W_h    = (const float*)d_in[3];
    const float* b_h    = (const float*)d_in[4];
    const float* dw_h   = (const float*)d_in[5];
    const float* ln_qk_g= (const float*)d_in[6];
    const float* ln_qk_b= (const float*)d_in[7];
    const float* W_qk   = (const float*)d_in[8];
    const float* b_qk   = (const float*)d_in[9];
    const float* dw_qk  = (const float*)d_in[10];
    const float* gamma  = (const float*)d_in[11];
    const float* beta   = (const float*)d_in[12];
    const float* ln_o_g = (const float*)d_in[13];
    const float* ln_o_b = (const float*)d_in[14];
    const float* W_o    = (const float*)d_in[15];
    const float* b_o    = (const float*)d_in[16];
    const float* dw_o   = (const float*)d_in[17];
    float* out = (float*)d_out;

    unsigned char* pool;
    cudaGetSymbolAddress((void**)&pool, g_pool);
    float*         opre = (float*)(pool + O_OPRE);
    __nv_bfloat16* lnH  = (__nv_bfloat16*)(pool + O_LNH);
    __nv_bfloat16* wCat = (__nv_bfloat16*)(pool + O_WCAT);
    __nv_bfloat16* woTH = (__nv_bfloat16*)(pool + O_WOTH);
    float*         bCat = (float*)(pool + O_BCAT);
    float*         bO   = (float*)(pool + O_BO);
    __nv_bfloat16* hB   = (__nv_bfloat16*)(pool + O_HB);
    __nv_bfloat16* hid  = (__nv_bfloat16*)(pool + O_HID);
    __nv_bfloat16* attB = (__nv_bfloat16*)(pool + O_ATT);
    __nv_bfloat16* hTH  = (__nv_bfloat16*)(pool + O_HTH);
    float*         qk   = (float*)(pool + O_QK);
    __nv_bfloat16* qqH  = (__nv_bfloat16*)(pool + O_QQH);
    __nv_bfloat16* lqH  = (__nv_bfloat16*)(pool + O_LQH);
    __nv_bfloat16* qkH  = (__nv_bfloat16*)(pool + O_QKH);
    float*         lkF  = (float*)(pool + O_LKF);
    __nv_bfloat16* lkTH = (__nv_bfloat16*)(pool + O_LKTH);
    __nv_bfloat16* attH = (__nv_bfloat16*)(pool + O_ATTH);
    __nv_bfloat16* kvB  = (__nv_bfloat16*)(pool + O_KVB);

    cudaFuncSetAttribute(gemm_k, cudaFuncAttributeMaxDynamicSharedMemorySize, GSMEM);

    // 1. weight transposes with LN-gain folding
    trans_bf16_k<<<dim3(2048/32, 512/32, 1), 256>>>(W_h,  wCat,            512, 2048, ln_h_g);
    trans_bf16_k<<<dim3(128/32,  512/32, 1), 256>>>(W_qk, wCat + 2048*512, 512, 128,  ln_qk_g);
    trans_bf16_k<<<dim3(512/32, 1024/32, 1), 256>>>(W_o,  woTH,            1024, 512, ln_o_g);
    // 2. effective biases (single merged GEMV launch)
    bias_fold_all_k<<<2688, 256>>>(W_h, ln_h_b, b_h, W_qk, ln_qk_b, b_qk,
                                   W_o, ln_o_b, b_o, bCat, bO);
    // 3. fused shift + pure-xhat LN -> lnH
    ln_shift_k<<<NT, 256>>>(x, lnH);
    // 4. MERGED GEMM1+GEMM2 -> hB (bf16) / qk (f32), SiLU
    gemm_k<<<dim3(17, 128, 1), 256, GSMEM>>>(lnH, wCat, nullptr, nullptr, nullptr, qk, hB,
        NT, HIDc, Dd, 0, bCat, 1.f, F_SILU | F_BF16, 0, 0, 0, 0, 0);
    // 5. dwconv (bf16, float4 compute) -> hid, fused group-transpose -> hTH
    dwconv_bf16_k<<<dim3(32, 16, Bb), 256>>>(hB, dw_h, hid, hTH);
    // 6. dwconv(C=128) + fused offset-scale split
    dwconv_qsplit_k<<<dim3(2, 16, Bb), 256>>>((const float4*)qk, dw_qk, gamma, beta,
                                              qqH, lqH, qkH, lkF);
    // 7. lin_k per-group transpose -> lkT [bg,128,256]
    trans_bf16_k<<<dim3(4, 8, 64), 256>>>(lkF, lkTH, 256, 128, nullptr);
    // 8. scores -> attH (relu^2 causal)
    gemm_k<<<dim3(2, 2, 64), 256, GSMEM>>>(qqH, qkH, nullptr, nullptr, nullptr, nullptr, attH,
        GRP, GRP, DQK, 0, nullptr, 1.f/GRP, F_SCORE,
        (long long)GRP*DQK, (long long)GRP*DQK, 0, 0, (long long)GRP*GRP);
    // 9. lin kv -> kvB (bf16, coalesced)
    gemm_k<<<dim3(1, 16, 64), 256, GSMEM>>>(hTH, lkTH, nullptr, nullptr, nullptr, nullptr, kvB,
        HIDc, DQK, GRP, 0, nullptr, 1.f/GRP, F_BF16,
        (long long)HIDc*GRP, (long long)DQK*GRP, 0, 0, (long long)HIDc*DQK);
    // 10. exclusive group cumsum, in place on kvB
    cumsum_bf16_k<<<(int)(((size_t)Bb*2048*64 + 255)/256), 256>>>(kvB);
    // 11. MERGED quad-out + lin-out -> attB (bf16)
    gemm_k<<<dim3(16, 2, 64), 256, GSMEM>>>(attH, hTH, lqH, kvB, nullptr, nullptr, attB,
        GRP, HIDc, GRP, DQK, nullptr, 1.f, F_TRIA | F_BF16,
        (long long)GRP*GRP, (long long)HIDc*GRP,
        (long long)GRP*DQK, (long long)HIDc*DQK, (long long)GRP*HIDc);
    // 12. fused gating (bf16 in) + pure-xhat LN_o -> lnH
    gate_ln_k<<<NT, 256>>>(attB, hid, lnH);
    // 13. GEMM3 -> opre (f32, SiLU, folded gains/bias)
    gemm_k<<<dim3(4, 128, 1), 256, GSMEM>>>(lnH, woTH, nullptr, nullptr, opre, nullptr, nullptr,
        NT, Dd, 2*Dd, 0, bO, 1.f, F_SILU, 0, 0, 0, 0, 0);
    // 14. dwconv + x residual -> out (f32)
    dwconv4_k<<<dim3(8, 16, Bb), 256>>>((const float4*)opre, dw_o, (const float4*)x,
                                        (float4*)out, Dd);
}

// round 17
// speedup vs baseline: 1.1534x; 1.0153x over previous
#include <cuda_runtime.h>
#include <cuda_bf16.h>
#include <cstdint>

#define Bb    8
#define Nn    2048
#define Dd    512
#define HIDc  2048
#define DQK   128
#define GRP   256
#define Gg    8
#define NT    (Bb*Nn)
#define Ee    1024
#define KK    17

// ================= warp MMA / async helpers =================
__device__ __forceinline__ uint32_t smem_to_u32(const void* p) {
    uint32_t a;
    asm("{ .reg .u64 t; cvta.to.shared.u64 t, %1; cvt.u32.u64 %0, t; }" : "=r"(a) : "l"(p));
    return a;
}
__device__ __forceinline__ void ldsm4(uint32_t* r, uint32_t addr) {
    asm volatile("ldmatrix.sync.aligned.m8n8.x4.shared.b16 {%0,%1,%2,%3}, [%4];"
        : "=r"(r[0]), "=r"(r[1]), "=r"(r[2]), "=r"(r[3]) : "r"(addr));
}
__device__ __forceinline__ void mma16816(float* c, const uint32_t* a, uint32_t b0, uint32_t b1) {
    asm volatile(
        "mma.sync.aligned.m16n8k16.row.col.f32.bf16.bf16.f32 "
        "{%0,%1,%2,%3}, {%4,%5,%6,%7}, {%8,%9}, {%0,%1,%2,%3};"
        : "+f"(c[0]), "+f"(c[1]), "+f"(c[2]), "+f"(c[3])
        : "r"(a[0]), "r"(a[1]), "r"(a[2]), "r"(a[3]), "r"(b0), "r"(b1));
}
__device__ __forceinline__ void cp16(uint32_t dst, const void* src) {
    asm volatile("cp.async.cg.shared.global [%0], [%1], 16;" :: "r"(dst), "l"(src));
}
#define CP_COMMIT() asm volatile("cp.async.commit_group;" ::: "memory")
#define CP_WAIT(N)  asm volatile("cp.async.wait_group %0;" :: "n"(N) : "memory")

#define F_SILU  1
#define F_SCORE 4
#define F_TRIA  16
#define F_BF16  32

// ================= scratch pool =================
#define SZF(n) ((size_t)(n)*4)
#define SZB(n) ((size_t)(n)*2)
static constexpr size_t O_OPRE = 0;                                 // f32 [NT,512]
static constexpr size_t O_LNH  = O_OPRE + SZF((size_t)NT*512);      // bf16 [NT,1024]
static constexpr size_t O_WCAT = O_LNH  + SZB((size_t)NT*1024);     // bf16 [2176,512]
static constexpr size_t O_WOTH = O_WCAT + SZB(2176*512);            // bf16 [512,1024]
static constexpr size_t O_BCAT = O_WOTH + SZB(512*1024);            // f32 [2176]
static constexpr size_t O_BO   = O_BCAT + SZF(2176);                // f32 [512]
static constexpr size_t O_HB   = O_BO   + SZF(512);                 // bf16 [NT,2048] (h)
static constexpr size_t O_HID  = O_HB   + SZB((size_t)NT*2048);     // bf16 [NT,2048]
static constexpr size_t O_ATT  = O_HID  + SZB((size_t)NT*2048);     // bf16 [NT,2048]
static constexpr size_t O_HTH  = O_ATT  + SZB((size_t)NT*2048);     // bf16 [bg,2048,256]
static constexpr size_t O_QK   = O_HTH  + SZB((size_t)NT*2048);     // f32 [NT,128]
static constexpr size_t O_QQH  = O_QK   + SZF((size_t)NT*128);      // bf16 [NT,128] x3
static constexpr size_t O_LQH  = O_QQH  + SZB((size_t)NT*128);
static constexpr size_t O_QKH  = O_LQH  + SZB((size_t)NT*128);
static constexpr size_t O_LKF  = O_QKH  + SZB((size_t)NT*128);      // f32 [NT,128]
static constexpr size_t O_LKTH = O_LKF  + SZF((size_t)NT*128);      // bf16 [bg,128,256]
static constexpr size_t O_ATTH = O_LKTH + SZB((size_t)NT*128);      // bf16 [bg,256,256]
static constexpr size_t O_KVB  = O_ATTH + SZB((size_t)64*256*256);  // bf16 [bg,2048,128]
static constexpr size_t O_END  = O_KVB  + SZB((size_t)64*2048*128);
__device__ __align__(1024) unsigned char g_pool[O_END];

__device__ __forceinline__ uint32_t pack_bf2(float v0, float v1) {
    __nv_bfloat16 h0 = __float2bfloat16(v0), h1 = __float2bfloat16(v1);
    return ((uint32_t)__bfloat16_as_ushort(h1) << 16) | __bfloat16_as_ushort(h0);
}
__device__ __forceinline__ void unpk4(uint2 u, float* f) {
    f[0] = __bfloat162float(__ushort_as_bfloat16((unsigned short)(u.x & 0xffff)));
    f[1] = __bfloat162float(__ushort_as_bfloat16((unsigned short)(u.x >> 16)));
    f[2] = __bfloat162float(__ushort_as_bfloat16((unsigned short)(u.y & 0xffff)));
    f[3] = __bfloat162float(__ushort_as_bfloat16((unsigned short)(u.y >> 16)));
}

// ================= prep kernels =================
__global__ void bias_fold_all_k(const float* __restrict__ W_h,  const float* __restrict__ lnb_h,
                                const float* __restrict__ b_h,
                                const float* __restrict__ W_qk, const float* __restrict__ lnb_qk,
                                const float* __restrict__ b_qk,
                                const float* __restrict__ W_o,  const float* __restrict__ lnb_o,
                                const float* __restrict__ b_o,
                                float* __restrict__ bCat, float* __restrict__ bO) {
    int blk = blockIdx.x;
    const float *W, *lnb, *bias; float* out; int K, N, n;
    if (blk < 2048)      { W = W_h;  lnb = lnb_h;  bias = b_h;  out = bCat;        K = 512;  N = 2048; n = blk; }
    else if (blk < 2176) { W = W_qk; lnb = lnb_qk; bias = b_qk; out = bCat + 2048; K = 512;  N = 128;  n = blk - 2048; }
    else                 { W = W_o;  lnb = lnb_o;  bias = b_o;  out = bO;          K = 1024; N = 512;  n = blk - 2176; }
    float s = 0.f;
    for (int k = threadIdx.x; k < K; k += blockDim.x)
        s += lnb[k] * W[(size_t)k*N + n];
    #pragma unroll
    for (int o = 16; o; o >>= 1) s += __shfl_xor_sync(~0u, s, o);
    __shared__ float sh[8];
    int w = threadIdx.x >> 5, l = threadIdx.x & 31;
    if (l == 0) sh[w] = s;
    __syncthreads();
    if (threadIdx.x == 0) {
        float ts = bias[n];
        for (int i = 0; i < (int)(blockDim.x >> 5); i++) ts += sh[i];
        out[n] = ts;
    }
}

// fused token-shift + pure-xhat LN (C=512) -> bf16
__global__ void ln_shift_k(const float* __restrict__ x, __nv_bfloat16* __restrict__ oh) {
    long t = blockIdx.x;
    int n = (int)(t % Nn);
    int i = threadIdx.x;
    const float2* xr = (const float2*)(x + t*Dd);
    const float2* xp = (const float2*)(x + (t-1)*Dd);
    float2 v;
    if (i < 128) v = (n == 0) ? make_float2(0.f, 0.f) : xp[i];
    else         v = xr[i];
    float s = v.x + v.y, s2 = v.x*v.x + v.y*v.y;
    #pragma unroll
    for (int o = 16; o; o >>= 1) {
        s  += __shfl_xor_sync(~0u, s,  o);
        s2 += __shfl_xor_sync(~0u, s2, o);
    }
    __shared__ float shs[8], shs2[8], smu, sinv;
    int w = i >> 5, l = i & 31;
    if (l == 0) { shs[w] = s; shs2[w] = s2; }
    __syncthreads();
    if (i == 0) {
        float ts = 0.f, ts2 = 0.f;
        for (int k = 0; k < 8; k++) { ts += shs[k]; ts2 += shs2[k]; }
        float mu = ts / Dd;
        smu = mu; sinv = rsqrtf(ts2 / Dd - mu*mu + 1e-5f);
    }
    __syncthreads();
    float mu = smu, inv = sinv;
    ((uint32_t*)(oh + t*Dd))[i] = pack_bf2((v.x - mu)*inv, (v.y - mu)*inv);
}

// fused gating + pure-xhat LN(1024), bf16 in -> bf16 out
__global__ void gate_ln_k(const __nv_bfloat16* __restrict__ att,
                          const __nv_bfloat16* __restrict__ hid,
                          __nv_bfloat16* __restrict__ oh) {
    long row = blockIdx.x;
    int i = threadIdx.x;
    float av[4], au[4], v[4], u[4], t[4];
    unpk4(((const uint2*)(att + row*HIDc))[i],      av);
    unpk4(((const uint2*)(att + row*HIDc + Ee))[i], au);
    unpk4(((const uint2*)(hid + row*HIDc))[i],      v);
    unpk4(((const uint2*)(hid + row*HIDc + Ee))[i], u);
    float s = 0.f, s2 = 0.f;
    #pragma unroll
    for (int j = 0; j < 4; j++) {
        t[j] = au[j] * v[j] * (1.f / (1.f + expf(-(av[j] * u[j]))));
        s += t[j]; s2 += t[j]*t[j];
    }
    #pragma unroll
    for (int o = 16; o; o >>= 1) {
        s  += __shfl_xor_sync(~0u, s,  o);
        s2 += __shfl_xor_sync(~0u, s2, o);
    }
    __shared__ float shs[8], shs2[8], smu, sinv;
    int w = i >> 5, l = i & 31;
    if (l == 0) { shs[w] = s; shs2[w] = s2; }
    __syncthreads();
    if (i == 0) {
        float ts = 0.f, ts2 = 0.f;
        for (int k = 0; k < 8; k++) { ts += shs[k]; ts2 += shs2[k]; }
        float mu = ts / 1024.f;
        smu = mu; sinv = rsqrtf(ts2 / 1024.f - mu*mu + 1e-5f);
    }
    __syncthreads();
    float mu = smu, inv = sinv;
    ((uint2*)(oh + row*1024))[i] = make_uint2(
        pack_bf2((t[0]-mu)*inv, (t[1]-mu)*inv),
        pack_bf2((t[2]-mu)*inv, (t[3]-mu)*inv));
}

// transpose fp32 [R,C] -> bf16 [C,R], optional per-input-row gain, batched via z
__global__ void trans_bf16_k(const float* __restrict__ in,
                             __nv_bfloat16* __restrict__ oh, int R, int C,
                             const float* __restrict__ gain) {
    __shared__ float s[32][36];
    size_t bz = (size_t)blockIdx.z * R * C;
    int c0 = blockIdx.x * 32, r0 = blockIdx.y * 32;
    int t = threadIdx.x;
    {
        int r = t >> 3, c4 = (t & 7) * 4;
        float4 v = *(const float4*)(in + bz + (size_t)(r0 + r)*C + c0 + c4);
        if (gain) {
            float gv = gain[r0 + r];
            v.x *= gv; v.y *= gv; v.z *= gv; v.w *= gv;
        }
        *(float4*)&s[r][c4] = v;
    }
    __syncthreads();
    {
        int c = t & 31, rg = (t >> 5) * 4;
        uint32_t h01 = pack_bf2(s[rg][c],   s[rg+1][c]);
        uint32_t h23 = pack_bf2(s[rg+2][c], s[rg+3][c]);
        size_t o = bz + (size_t)(c0 + c)*R + r0 + rg;
        *(uint2*)(oh + o) = make_uint2(h01, h23);
    }
}

// depthwise conv K=17 + residual, bf16 in/out (C=2048), float4 smem compute,
// fused group-transpose -> ht
__global__ void dwconv_bf16_k(const __nv_bfloat16* __restrict__ h, const float* __restrict__ dw,
                              __nv_bfloat16* __restrict__ out, __nv_bfloat16* __restrict__ ht) {
    const int C = HIDc, CT4 = 16, NTile = 128, HALO = 8;
    __shared__ float4 sh[NTile + 2*HALO][CT4];
    __shared__ float4 sdw[KK][CT4];
    int b = blockIdx.z, n0 = blockIdx.y * NTile, c0 = blockIdx.x * 64;
    for (int idx = threadIdx.x; idx < 144*8; idx += 256) {
        int r = idx >> 3, q = idx & 7;
        int n = n0 - HALO + r;
        float4 f0, f1;
        if (n >= 0 && n < Nn) {
            uint4 uv = *(const uint4*)(h + ((size_t)b*Nn + n)*C + c0 + q*8);
            float tmp[4];
            unpk4(make_uint2(uv.x, uv.y), tmp);
            f0 = make_float4(tmp[0], tmp[1], tmp[2], tmp[3]);
            unpk4(make_uint2(uv.z, uv.w), tmp);
            f1 = make_float4(tmp[0], tmp[1], tmp[2], tmp[3]);
        } else {
            f0 = make_float4(0,0,0,0); f1 = f0;
        }
        sh[r][q*2]   = f0;
        sh[r][q*2+1] = f1;
    }
    for (int idx = threadIdx.x; idx < KK*CT4; idx += 256) {
        int k = idx >> 4, c = idx & 15;
        const float* w = dw + k*C + c0 + c*4;
        sdw[k][c] = make_float4(w[0], w[1], w[2], w[3]);
    }
    __syncthreads();
    float4 accs[8];
    #pragma unroll
    for (int e = 0; e < 8; e++) {
        int idx = threadIdx.x + e*256;
        int r = idx >> 4, c = idx & 15;
        float4 acc = sh[r + HALO][c];
        #pragma unroll
        for (int k = 0; k < KK; k++) {
            float4 a = sh[r + k][c], w = sdw[k][c];
            acc.x += a.x*w.x; acc.y += a.y*w.y; acc.z += a.z*w.z; acc.w += a.w*w.w;
        }
        accs[e] = acc;
        *(uint2*)(out + ((size_t)b*Nn + n0 + r)*C + c0 + c*4) =
            make_uint2(pack_bf2(acc.x, acc.y), pack_bf2(acc.z, acc.w));
    }
    __syncthreads();
    float* sout = (float*)sh;
    #pragma unroll
    for (int e = 0; e < 8; e++) {
        int idx = threadIdx.x + e*256;
        int r = idx >> 4, c = idx & 15;
        float* p = &sout[r*65 + c*4];
        p[0] = accs[e].x; p[1] = accs[e].y; p[2] = accs[e].z; p[3] = accs[e].w;
    }
    __syncthreads();
    int g = n0 >> 8, nloc = n0 & 255;
    size_t basebg = ((size_t)(b*Gg + g)*C + c0) * 256 + nloc;
    #pragma unroll
    for (int e = 0; e < 8; e++) {
        int idx = threadIdx.x + e*256;
        int cc = idx >> 5, r4 = (idx & 31) * 4;
        float v0 = sout[(r4+0)*65 + cc];
        float v1 = sout[(r4+1)*65 + cc];
        float v2 = sout[(r4+2)*65 + cc];
        float v3 = sout[(r4+3)*65 + cc];
        *(uint2*)(ht + basebg + (size_t)cc*256 + r4) =
            make_uint2(pack_bf2(v0, v1), pack_bf2(v2, v3));
    }
}

// f32 depthwise conv K=17 + residual (+ extra residual) — final path
__global__ void dwconv4_k(const float4* __restrict__ h4, const float* __restrict__ dw,
                          const float4* __restrict__ extra4, float4* __restrict__ out4, int C) {
    const int CT4 = 16, NTile = 128, HALO = 8;
    __shared__ float4 sh[NTile + 2*HALO][CT4];
    __shared__ float4 sdw[KK][CT4];
    int b = blockIdx.z, n0 = blockIdx.y * NTile, c0 = blockIdx.x * CT4;
    int C4 = C >> 2;
    const float4* base = h4 + (size_t)b*Nn*C4 + c0;
    for (int idx = threadIdx.x; idx < (NTile + 2*HALO)*CT4; idx += blockDim.x) {
        int r = idx >> 4, c = idx & 15;
        int n = n0 - HALO + r;
        sh[r][c] = (n >= 0 && n < Nn) ? base[(size_t)n*C4 + c] : make_float4(0,0,0,0);
    }
    for (int idx = threadIdx.x; idx < KK*CT4; idx += blockDim.x) {
        int k = idx >> 4, c = idx & 15;
        const float* w = dw + k*C + (c0 + c)*4;
        sdw[k][c] = make_float4(w[0], w[1], w[2], w[3]);
    }
    __syncthreads();
    for (int idx = threadIdx.x; idx < NTile*CT4; idx += blockDim.x) {
        int r = idx >> 4, c = idx & 15;
        float4 acc = sh[r + HALO][c];
        #pragma unroll
        for (int k = 0; k < KK; k++) {
            float4 a = sh[r + k][c], w = sdw[k][c];
            acc.x += a.x*w.x; acc.y += a.y*w.y; acc.z += a.z*w.z; acc.w += a.w*w.w;
        }
        size_t o = (size_t)b*Nn*C4 + (size_t)(n0 + r)*C4 + c0 + c;
        if (extra4) {
            float4 ev = extra4[o];
            acc.x += ev.x; acc.y += ev.y; acc.z += ev.z; acc.w += ev.w;
        }
        out4[o] = acc;
    }
}

// dwconv (C=128) + residual, fused offset-scale split epilogue
__global__ void dwconv_qsplit_k(const float4* __restrict__ h4, const float* __restrict__ dw,
                                const float* __restrict__ gamma, const float* __restrict__ beta,
                                __nv_bfloat16* __restrict__ qqh, __nv_bfloat16* __restrict__ lqh,
                                __nv_bfloat16* __restrict__ qkh, float* __restrict__ lkf) {
    const int CT4 = 16, NTile = 128, HALO = 8, C4 = 32;
    __shared__ float4 sh[NTile + 2*HALO][CT4];
    __shared__ float4 sdw[KK][CT4];
    __shared__ float sg[4][64], sb[4][64];
    int b = blockIdx.z, n0 = blockIdx.y * NTile, c0 = blockIdx.x * CT4;
    const float4* base = h4 + (size_t)b*Nn*C4 + c0;
    for (int idx = threadIdx.x; idx < (NTile + 2*HALO)*CT4; idx += blockDim.x) {
        int r = idx >> 4, c = idx & 15;
        int n = n0 - HALO + r;
        sh[r][c] = (n >= 0 && n < Nn) ? base[(size_t)n*C4 + c] : make_float4(0,0,0,0);
    }
    for (int idx = threadIdx.x; idx < KK*CT4; idx += blockDim.x) {
        int k = idx >> 4, c = idx & 15;
        const float* w = dw + k*DQK + (c0 + c)*4;
        sdw[k][c] = make_float4(w[0], w[1], w[2], w[3]);
    }
    {
        int s = threadIdx.x >> 6, j = threadIdx.x & 63;
        sg[s][j] = gamma[s*DQK + c0*4 + j];
        sb[s][j] = beta [s*DQK + c0*4 + j];
    }
    __syncthreads();
    #pragma unroll
    for (int e = 0; e < 8; e++) {
        int idx = threadIdx.x + e*256;
        int r = idx >> 4, c = idx & 15;
        float4 acc = sh[r + HALO][c];
        #pragma unroll
        for (int k = 0; k < KK; k++) {
            float4 a = sh[r + k][c], w = sdw[k][c];
            acc.x += a.x*w.x; acc.y += a.y*w.y; acc.z += a.z*w.z; acc.w += a.w*w.w;
        }
        float av[4] = {acc.x, acc.y, acc.z, acc.w};
        int chl = c*4;
        float q[4], lq[4], qk[4], lk[4];
        #pragma unroll
        for (int j = 0; j < 4; j++) {
            q[j]  = av[j]*sg[0][chl+j] + sb[0][chl+j];
            lq[j] = av[j]*sg[1][chl+j] + sb[1][chl+j];
            qk[j] = av[j]*sg[2][chl+j] + sb[2][chl+j];
            lk[j] = av[j]*sg[3][chl+j] + sb[3][chl+j];
        }
        size_t ob = ((size_t)b*Nn + n0 + r)*DQK + (c0 + c)*4;
        *(uint2*)(qqh + ob) = make_uint2(pack_bf2(q[0],q[1]),  pack_bf2(q[2],q[3]));
        *(uint2*)(lqh + ob) = make_uint2(pack_bf2(lq[0],lq[1]), pack_bf2(lq[2],lq[3]));
        *(uint2*)(qkh + ob) = make_uint2(pack_bf2(qk[0],qk[1]), pack_bf2(qk[2],qk[3]));
        *(float4*)(lkf + ob) = make_float4(lk[0], lk[1], lk[2], lk[3]);
    }
}

// in-place exclusive group-cumsum over bf16 kv [b][g][2048*128]
__global__ void cumsum_bf16_k(__nv_bfloat16* kv) {
    const size_t S = (size_t)2048*128;
    long i2 = (long)blockIdx.x * blockDim.x + threadIdx.x;
    if (i2 >= (long)Bb*(S/2)) return;
    size_t b = (size_t)i2 / (S/2), r2 = (size_t)i2 % (S/2);
    size_t base2 = b*Gg*(S/2) + r2;
    float s0 = 0.f, s1 = 0.f;
    uint32_t* kv2 = (uint32_t*)kv;
    #pragma unroll
    for (int g = 0; g < Gg; g++) {
        size_t o2 = base2 + (size_t)g*(S/2);
        uint32_t uv = kv2[o2];
        float v0 = __bfloat162float(__ushort_as_bfloat16((unsigned short)(uv & 0xffff)));
        float v1 = __bfloat162float(__ushort_as_bfloat16((unsigned short)(uv >> 16)));
        kv2[o2] = pack_bf2(s0, s1);
        s0 += v0; s1 += v1;
    }
}

// ================= HMMA bf16 GEMM — two-part K, split-C, staged bf16 epilogue ===
#define LDA 72
#define STG_BYTES 36864
#define GSMEM (2*STG_BYTES)

__global__ void __launch_bounds__(256, 2) gemm_k(
    const __nv_bfloat16* __restrict__ A1, const __nv_bfloat16* __restrict__ B1,
    const __nv_bfloat16* __restrict__ A2, const __nv_bfloat16* __restrict__ B2,
    float* C, float* Cq, __nv_bfloat16* Ch,
    int M, int N, int K1, int K2, const float* __restrict__ bias, float alpha, int flags,
    long long sA1, long long sB1, long long sA2, long long sB2, long long sC)
{
    extern __shared__ __align__(16) unsigned char smem[];
    uint32_t sbase = smem_to_u32(smem);
    int tid = threadIdx.x, lane = tid & 31, wid = tid >> 5;
    int wm = wid & 3, wn = wid >> 2;
    int brow = blockIdx.y * 128, bcol = blockIdx.x * 128;
    long long bz = blockIdx.z;
    A1 += bz*sA1; B1 += bz*sB1;
    if (A2) { A2 += bz*sA2; B2 += bz*sB2; }
    if (C)  C  += bz*sC;
    if (Ch) Ch += bz*sC;

    if ((flags & F_SCORE) && bcol > brow) {
        uint4 z = make_uint4(0,0,0,0);
        for (int e = tid; e < 2048; e += 256) {
            int row = e >> 4, seg = e & 15;
            *(uint4*)(Ch + (size_t)(brow + row)*N + bcol + seg*8) = z;
        }
        return;
    }

    float acc[2][8][4];
    #pragma unroll
    for (int i = 0; i < 2; i++)
        #pragma unroll
        for (int j = 0; j < 8; j++)
            #pragma unroll
            for (int q = 0; q < 4; q++) acc[i][j][q] = 0.f;

    uint32_t aOff = (uint32_t)(((wm*32 + (lane & 15)) * LDA + (lane >> 4)*8) * 2);
    uint32_t bOff = (uint32_t)(((wn*64 + ((lane >> 4) & 1)*8 + (lane & 7)) * LDA
                                + ((lane >> 3) & 1)*8) * 2) + 18432;
    const int ldr = tid >> 3, lds2 = tid & 7;

    int KC1 = K1 >> 6;
    if (flags & F_TRIA) {
        int kc = (brow + 128) >> 6;
        if (kc < KC1) KC1 = kc;
    }
    const int KC2 = K2 >> 6;
    const int KC = KC1 + KC2;

    auto issue = [&](int it) {
        const __nv_bfloat16 *Ap, *Bp; int k0, Kst;
        if (it < KC1) { Ap = A1; Bp = B1; k0 = it << 6;          Kst = K1; }
        else          { Ap = A2; Bp = B2; k0 = (it - KC1) << 6;  Kst = K2; }
        uint32_t sa = sbase + (uint32_t)(it & 1)*STG_BYTES;
        #pragma unroll
        for (int e = 0; e < 4; e++) {
            int r = ldr + e*32;
            cp16(sa + (uint32_t)(r*144 + lds2*16),
                 Ap + (size_t)(brow + r)*Kst + k0 + lds2*8);
            cp16(sa + 18432u + (uint32_t)(r*144 + lds2*16),
                 Bp + (size_t)(bcol + r)*Kst + k0 + lds2*8);
        }
        CP_COMMIT();
    };

    issue(0);
    for (int it = 0; it < KC; ++it) {
        if (it + 1 < KC) { issue(it + 1); CP_WAIT(1); }
        else             { CP_WAIT(0); }
        __syncthreads();
        uint32_t stg = sbase + (uint32_t)(it & 1)*STG_BYTES;
        uint32_t aB = stg + aOff, bB = stg + bOff;
        #pragma unroll
        for (int kk = 0; kk < 4; kk++) {
            uint32_t af[2][4], bfr[4][4];
            #pragma unroll
            for (int i = 0; i < 2; i++)
                ldsm4(af[i], aB + (uint32_t)((i*16*LDA + kk*16) * 2));
            #pragma unroll
            for (int p = 0; p < 4; p++)
                ldsm4(bfr[p], bB + (uint32_t)((p*16*LDA + kk*16) * 2));
            #pragma unroll
            for (int i = 0; i < 2; i++)
                #pragma unroll
                for (int j = 0; j < 8; j++)
                    mma16816(acc[i][j], af[i], bfr[j>>1][(j&1)*2], bfr[j>>1][(j&1)*2+1]);
        }
        __syncthreads();
    }

    // ---- epilogue: transform values in place ----
    int g = lane >> 2, c2 = (lane & 3)*2;
    #pragma unroll
    for (int i = 0; i < 2; i++) {
        #pragma unroll
        for (int j = 0; j < 8; j++) {
            #pragma unroll
            for (int rr = 0; rr < 2; rr++) {
                int row = brow + wm*32 + i*16 + g + rr*8;
                int col = bcol + wn*64 + j*8 + c2;
                float v0 = acc[i][j][rr*2+0] * alpha;
                float v1 = acc[i][j][rr*2+1] * alpha;
                if (flags & F_SCORE) {
                    v0 = fmaxf(v0, 0.f); v0 *= v0;
                    v1 = fmaxf(v1, 0.f); v1 *= v1;
                    if (col     > row) v0 = 0.f;
                    if (col + 1 > row) v1 = 0.f;
                } else {
                    if (bias) { v0 += bias[col]; v1 += bias[col+1]; }
                    if (flags & F_SILU) {
                        v0 = v0 / (1.f + expf(-v0));
                        v1 = v1 / (1.f + expf(-v1));
                    }
                }
                acc[i][j][rr*2+0] = v0;
                acc[i][j][rr*2+1] = v1;
            }
        }
    }

    // ---- store ----
    bool toCq = (Cq && bcol >= 2048);
    if ((flags & (F_BF16 | F_SCORE)) && !toCq) {
        // stage bf16 tile in smem ([128][136] bf16), then coalesced uint4 stores
        __nv_bfloat16* st = (__nv_bfloat16*)smem;
        #pragma unroll
        for (int i = 0; i < 2; i++)
            #pragma unroll
            for (int j = 0; j < 8; j++)
                #pragma unroll
                for (int rr = 0; rr < 2; rr++) {
                    int rl = wm*32 + i*16 + g + rr*8;
                    int cl = wn*64 + j*8 + c2;
                    *(uint32_t*)(st + rl*136 + cl) =
                        pack_bf2(acc[i][j][rr*2], acc[i][j][rr*2+1]);
                }
        __syncthreads();
        #pragma unroll
        for (int e = 0; e < 8; e++) {
            int idx = tid + e*256;
            int r = idx >> 4, seg = idx & 15;
            *(uint4*)(Ch + (size_t)(brow + r)*N + bcol + seg*8) =
                *(const uint4*)(st + r*136 + seg*8);
        }
    } else {
        #pragma unroll
        for (int i = 0; i < 2; i++)
            #pragma unroll
            for (int j = 0; j < 8; j++)
                #pragma unroll
                for (int rr = 0; rr < 2; rr++) {
                    int row = brow + wm*32 + i*16 + g + rr*8;
                    int col = bcol + wn*64 + j*8 + c2;
                    float v0 = acc[i][j][rr*2], v1 = acc[i][j][rr*2+1];
                    if (toCq)
                        *(float2*)(Cq + (size_t)row*DQK + col - 2048) = make_float2(v0, v1);
                    else
                        *(float2*)(C + (size_t)row*N + col) = make_float2(v0, v1);
                }
    }
}

// ================= launcher =================
extern "C" void kernel_launch(void* const* d_in, const int* in_sizes, int n_in,
                              void* d_out, int out_size) {
    const float* x      = (const float*)d_in[0];
    const float* ln_h_g = (const float*)d_in[1];
    const float* ln_h_b = (const float*)d_in[2];
    const float* W_h    = (const float*)d_in[3];
    const float* b_h    = (const float*)d_in[4];
    const float* dw_h   = (const float*)d_in[5];
    const float* ln_qk_g= (const float*)d_in[6];
    const float* ln_qk_b= (const float*)d_in[7];
    const float* W_qk   = (const float*)d_in[8];
    const float* b_qk   = (const float*)d_in[9];
    const float* dw_qk  = (const float*)d_in[10];
    const float* gamma  = (const float*)d_in[11];
    const float* beta   = (const float*)d_in[12];
    const float* ln_o_g = (const float*)d_in[13];
    const float* ln_o_b = (const float*)d_in[14];
    const float* W_o    = (const float*)d_in[15];
    const float* b_o    = (const float*)d_in[16];
    const float* dw_o   = (const float*)d_in[17];
    float* out = (float*)d_out;

    unsigned char* pool;
    cudaGetSymbolAddress((void**)&pool, g_pool);
    float*         opre = (float*)(pool + O_OPRE);
    __nv_bfloat16* lnH  = (__nv_bfloat16*)(pool + O_LNH);
    __nv_bfloat16* wCat = (__nv_bfloat16*)(pool + O_WCAT);
    __nv_bfloat16* woTH = (__nv_bfloat16*)(pool + O_WOTH);
    float*         bCat = (float*)(pool + O_BCAT);
    float*         bO   = (float*)(pool + O_BO);
    __nv_bfloat16* hB   = (__nv_bfloat16*)(pool + O_HB);
    __nv_bfloat16* hid  = (__nv_bfloat16*)(pool + O_HID);
    __nv_bfloat16* attB = (__nv_bfloat16*)(pool + O_ATT);
    __nv_bfloat16* hTH  = (__nv_bfloat16*)(pool + O_HTH);
    float*         qk   = (float*)(pool + O_QK);
    __nv_bfloat16* qqH  = (__nv_bfloat16*)(pool + O_QQH);
    __nv_bfloat16* lqH  = (__nv_bfloat16*)(pool + O_LQH);
    __nv_bfloat16* qkH  = (__nv_bfloat16*)(pool + O_QKH);
    float*         lkF  = (float*)(pool + O_LKF);
    __nv_bfloat16* lkTH = (__nv_bfloat16*)(pool + O_LKTH);
    __nv_bfloat16* attH = (__nv_bfloat16*)(pool + O_ATTH);
    __nv_bfloat16* kvB  = (__nv_bfloat16*)(pool + O_KVB);

    cudaFuncSetAttribute(gemm_k, cudaFuncAttributeMaxDynamicSharedMemorySize, GSMEM);

    // 1. weight transposes with LN-gain folding
    trans_bf16_k<<<dim3(2048/32, 512/32, 1), 256>>>(W_h,  wCat,            512, 2048, ln_h_g);
    trans_bf16_k<<<dim3(128/32,  512/32, 1), 256>>>(W_qk, wCat + 2048*512, 512, 128,  ln_qk_g);
    trans_bf16_k<<<dim3(512/32, 1024/32, 1), 256>>>(W_o,  woTH,            1024, 512, ln_o_g);
    // 2. effective biases (single merged GEMV launch)
    bias_fold_all_k<<<2688, 256>>>(W_h, ln_h_b, b_h, W_qk, ln_qk_b, b_qk,
                                   W_o, ln_o_b, b_o, bCat, bO);
    // 3. fused shift + pure-xhat LN -> lnH
    ln_shift_k<<<NT, 256>>>(x, lnH);
    // 4. MERGED GEMM1+GEMM2 -> hB (bf16) / qk (f32), SiLU
    gemm_k<<<dim3(17, 128, 1), 256, GSMEM>>>(lnH, wCat, nullptr, nullptr, nullptr, qk, hB,
        NT, HIDc, Dd, 0, bCat, 1.f, F_SILU | F_BF16, 0, 0, 0, 0, 0);
    // 5. dwconv (bf16, float4 compute) -> hid, fused group-transpose -> hTH
    dwconv_bf16_k<<<dim3(32, 16, Bb), 256>>>(hB, dw_h, hid, hTH);
    // 6. dwconv(C=128) + fused offset-scale split
    dwconv_qsplit_k<<<dim3(2, 16, Bb), 256>>>((const float4*)qk, dw_qk, gamma, beta,
                                              qqH, lqH, qkH, lkF);
    // 7. lin_k per-group transpose -> lkT [bg,128,256]
    trans_bf16_k<<<dim3(4, 8, 64), 256>>>(lkF, lkTH, 256, 128, nullptr);
    // 8. scores -> attH (relu^2 causal)
    gemm_k<<<dim3(2, 2, 64), 256, GSMEM>>>(qqH, qkH, nullptr, nullptr, nullptr, nullptr, attH,
        GRP, GRP, DQK, 0, nullptr, 1.f/GRP, F_SCORE,
        (long long)GRP*DQK, (long long)GRP*DQK, 0, 0, (long long)GRP*GRP);
    // 9. lin kv -> kvB (bf16, coalesced)
    gemm_k<<<dim3(1, 16, 64), 256, GSMEM>>>(hTH, lkTH, nullptr, nullptr, nullptr, nullptr, kvB,
        HIDc, DQK, GRP, 0, nullptr, 1.f/GRP, F_BF16,
        (long long)HIDc*GRP, (long long)DQK*GRP, 0, 0, (long long)HIDc*DQK);
    // 10. exclusive group cumsum, in place on kvB
    cumsum_bf16_k<<<(int)(((size_t)Bb*2048*64 + 255)/256), 256>>>(kvB);
    // 11. MERGED quad-out + lin-out -> attB (bf16)
    gemm_k<<<dim3(16, 2, 64), 256, GSMEM>>>(attH, hTH, lqH, kvB, nullptr, nullptr, attB,
        GRP, HIDc, GRP, DQK, nullptr, 1.f, F_TRIA | F_BF16,
        (long long)GRP*GRP, (long long)HIDc*GRP,
        (long long)GRP*DQK, (long long)HIDc*DQK, (long long)GRP*HIDc);
    // 12. fused gating (bf16 in) + pure-xhat LN_o -> lnH
    gate_ln_k<<<NT, 256>>>(attB, hid, lnH);
    // 13. GEMM3 -> opre (f32, SiLU, folded gains/bias)
    gemm_k<<<dim3(4, 128, 1), 256, GSMEM>>>(lnH, woTH, nullptr, nullptr, opre, nullptr, nullptr,
        NT, Dd, 2*Dd, 0, bO, 1.f, F_SILU, 0, 0, 0, 0, 0);
    // 14. dwconv + x residual -> out (f32)
    dwconv4_k<<<dim3(8, 16, Bb), 256>>>((const float4*)opre, dw_o, (const float4*)x,
                                        (float4*)out, Dd);
}